// round 5
// baseline (speedup 1.0000x reference)
#include <cuda_runtime.h>
#include <math.h>

#define DH 128
#define NMAX 50016
#define EMAX 800000

// ---------------- scratch (device globals; no allocation allowed) ----------------
__device__ float g_dinv[NMAX];
__device__ int   g_deg[NMAX];
__device__ int   g_rowptr[NMAX + 1];
__device__ int   g_cursor[NMAX];
__device__ int   g_adj[EMAX];
__device__ float g_h1[(size_t)NMAX * DH];   // dinv-scaled transformed features
__device__ float g_h2[(size_t)NMAX * DH];   // aggregated features
__device__ float g_sum[DH];
__device__ float g_sq[DH];
__device__ float g_bna[DH];                 // a = gamma * rstd
__device__ float g_bnb[DH];                 // b = beta - mu * a

// ---------------- CSR build ----------------
__global__ void k_zero_deg(int* deg, int n) {
    int i = blockIdx.x * blockDim.x + threadIdx.x;
    if (i < n) deg[i] = 0;
}

__global__ void k_count(const int* __restrict__ dst, int* deg, int E) {
    int e = blockIdx.x * blockDim.x + threadIdx.x;
    if (e < E) atomicAdd(&deg[dst[e]], 1);
}

// single block, 1024 threads: exclusive scan of deg -> rowptr/cursor, and dinv
__global__ __launch_bounds__(1024) void k_scan(const int* __restrict__ deg,
                                               int* rowptr, int* cursor,
                                               float* dinv, int n)
{
    __shared__ int sm[1024];
    const int T = 1024;
    int tid = threadIdx.x;
    int chunk = (n + T - 1) / T;
    int beg = tid * chunk;
    int end = min(beg + chunk, n);
    if (beg > n) beg = n;
    if (end < beg) end = beg;

    int s = 0;
    for (int i = beg; i < end; i++) s += deg[i];
    sm[tid] = s;
    __syncthreads();
    for (int off = 1; off < T; off <<= 1) {
        int v = (tid >= off) ? sm[tid - off] : 0;
        __syncthreads();
        sm[tid] += v;
        __syncthreads();
    }
    int run = sm[tid] - s;                  // exclusive prefix of this chunk
    for (int i = beg; i < end; i++) {
        int d = deg[i];
        rowptr[i] = run;
        cursor[i] = run;
        dinv[i] = rsqrtf((float)d + 1.0f);  // +1 self-loop
        run += d;
    }
    if (tid == T - 1) rowptr[n] = sm[T - 1];
}

__global__ void k_fill(const int* __restrict__ src, const int* __restrict__ dst,
                       int* cursor, int* adj, int E)
{
    int e = blockIdx.x * blockDim.x + threadIdx.x;
    if (e < E) {
        int d = dst[e];
        int p = atomicAdd(&cursor[d], 1);
        adj[p] = src[e];
    }
}

// ---------------- SGEMM: C[n,128] = op(A)[n,128] @ W[128,128], C scaled by dinv[row] ----------------
// 128x128 block tile, 256 threads, 8x8 per-thread register tile.
// op(A) = BN ? relu(A*bna+bnb) : A.  Block 0 zeroes BN-stat accumulators for the
// aggregation kernel launched after this gemm.
template <bool BN>
__global__ __launch_bounds__(256) void gemm128(
    const float* __restrict__ A, const float* __restrict__ W,
    float* __restrict__ C, const float* __restrict__ dinv,
    const float* __restrict__ bna, const float* __restrict__ bnb, int nrows)
{
    if (blockIdx.x == 0 && threadIdx.x < DH) {
        g_sum[threadIdx.x] = 0.f;
        g_sq[threadIdx.x] = 0.f;
    }
    __shared__ float sA[16][128];    // transposed: sA[k][r]
    __shared__ float sW[16][128];
    int tid = threadIdx.x;
    int tx = tid & 15, ty = tid >> 4;
    int row0 = blockIdx.x * 128;

    float acc[8][8];
#pragma unroll
    for (int i = 0; i < 8; i++)
#pragma unroll
        for (int j = 0; j < 8; j++) acc[i][j] = 0.f;

    for (int kt = 0; kt < 128; kt += 16) {
        // A tile: 128 rows x 16 cols = 512 float4, two per thread
#pragma unroll
        for (int i = 0; i < 2; i++) {
            int f = tid + i * 256;
            int r = f >> 2;
            int k4 = (f & 3) * 4;
            int gr = row0 + r;
            float4 v = (gr < nrows) ? *(const float4*)(A + (size_t)gr * 128 + kt + k4)
                                    : make_float4(0.f, 0.f, 0.f, 0.f);
            if (BN) {
                int c = kt + k4;
                v.x = fmaxf(v.x * bna[c + 0] + bnb[c + 0], 0.f);
                v.y = fmaxf(v.y * bna[c + 1] + bnb[c + 1], 0.f);
                v.z = fmaxf(v.z * bna[c + 2] + bnb[c + 2], 0.f);
                v.w = fmaxf(v.w * bna[c + 3] + bnb[c + 3], 0.f);
            }
            sA[k4 + 0][r] = v.x; sA[k4 + 1][r] = v.y;
            sA[k4 + 2][r] = v.z; sA[k4 + 3][r] = v.w;
        }
        // W tile: 16 x 128 = 512 float4, two per thread
#pragma unroll
        for (int i = 0; i < 2; i++) {
            int f = tid + i * 256;
            int kr = f >> 5;
            int c4 = (f & 31) * 4;
            *(float4*)&sW[kr][c4] = *(const float4*)(W + (size_t)(kt + kr) * 128 + c4);
        }
        __syncthreads();

#pragma unroll
        for (int k = 0; k < 16; k++) {
            float a[8], w[8];
            *(float4*)&a[0] = *(float4*)&sA[k][ty * 8];
            *(float4*)&a[4] = *(float4*)&sA[k][ty * 8 + 4];
            *(float4*)&w[0] = *(float4*)&sW[k][tx * 8];
            *(float4*)&w[4] = *(float4*)&sW[k][tx * 8 + 4];
#pragma unroll
            for (int i = 0; i < 8; i++)
#pragma unroll
                for (int j = 0; j < 8; j++) acc[i][j] += a[i] * w[j];
        }
        __syncthreads();
    }

#pragma unroll
    for (int i = 0; i < 8; i++) {
        int gr = row0 + ty * 8 + i;
        if (gr < nrows) {
            float di = dinv[gr];
            *(float4*)(C + (size_t)gr * 128 + tx * 8) =
                make_float4(acc[i][0] * di, acc[i][1] * di, acc[i][2] * di, acc[i][3] * di);
            *(float4*)(C + (size_t)gr * 128 + tx * 8 + 4) =
                make_float4(acc[i][4] * di, acc[i][5] * di, acc[i][6] * di, acc[i][7] * di);
        }
    }
}

// ---------------- SGEMM: C[n,40] = relu(A*bna+bnb)[n,128] @ W[128,40], scaled by dinv ----------------
__global__ __launch_bounds__(256) void gemm40(
    const float* __restrict__ A, const float* __restrict__ W,
    float* __restrict__ C, const float* __restrict__ dinv,
    const float* __restrict__ bna, const float* __restrict__ bnb, int nrows)
{
    __shared__ float sA[16][64];
    __shared__ float sW[16][40];
    int tid = threadIdx.x;
    int tx = tid & 15, ty = tid >> 4;
    int row0 = blockIdx.x * 64;

    float acc[4][3];
#pragma unroll
    for (int i = 0; i < 4; i++)
#pragma unroll
        for (int j = 0; j < 3; j++) acc[i][j] = 0.f;

    for (int kt = 0; kt < 128; kt += 16) {
        {
            int r = tid >> 2;
            int k4 = (tid & 3) * 4;
            int gr = row0 + r;
            float4 v = (gr < nrows) ? *(const float4*)(A + (size_t)gr * 128 + kt + k4)
                                    : make_float4(0.f, 0.f, 0.f, 0.f);
            int c = kt + k4;
            v.x = fmaxf(v.x * bna[c + 0] + bnb[c + 0], 0.f);
            v.y = fmaxf(v.y * bna[c + 1] + bnb[c + 1], 0.f);
            v.z = fmaxf(v.z * bna[c + 2] + bnb[c + 2], 0.f);
            v.w = fmaxf(v.w * bna[c + 3] + bnb[c + 3], 0.f);
            sA[k4 + 0][r] = v.x; sA[k4 + 1][r] = v.y;
            sA[k4 + 2][r] = v.z; sA[k4 + 3][r] = v.w;
        }
        for (int t = tid; t < 16 * 40; t += 256) {
            int kr = t / 40, c = t % 40;
            sW[kr][c] = W[(size_t)(kt + kr) * 40 + c];
        }
        __syncthreads();

#pragma unroll
        for (int k = 0; k < 16; k++) {
            float4 av = *(float4*)&sA[k][ty * 4];
            float a[4] = {av.x, av.y, av.z, av.w};
            float w0 = sW[k][tx];
            float w1 = sW[k][tx + 16];
            float w2 = (tx < 8) ? sW[k][tx + 32] : 0.f;
#pragma unroll
            for (int i = 0; i < 4; i++) {
                acc[i][0] += a[i] * w0;
                acc[i][1] += a[i] * w1;
                acc[i][2] += a[i] * w2;
            }
        }
        __syncthreads();
    }

#pragma unroll
    for (int i = 0; i < 4; i++) {
        int gr = row0 + ty * 4 + i;
        if (gr >= nrows) continue;
        float di = dinv[gr];
        C[(size_t)gr * 40 + tx]      = acc[i][0] * di;
        C[(size_t)gr * 40 + tx + 16] = acc[i][1] * di;
        if (tx < 8) C[(size_t)gr * 40 + tx + 32] = acc[i][2] * di;
    }
}

// ---------------- CSR gather aggregation, D=128 ----------------
// TWO nodes per warp with interleaved gathers (two independent dependency
// chains -> 8 outstanding LDG.128 with better overlap). Register BN stats.
template <bool STATS>
__global__ __launch_bounds__(256) void k_agg128(
    const float* __restrict__ hs, const int* __restrict__ rowptr,
    const int* __restrict__ adj, const float* __restrict__ dinv,
    const float* __restrict__ bias, float* __restrict__ out, int n)
{
    int tid = threadIdx.x;
    int warp = tid >> 5, lane = tid & 31;
    int g = lane * 4;
    float4 bv = __ldg((const float4*)(bias + g));

    float s0 = 0.f, s1 = 0.f, s2 = 0.f, s3 = 0.f;
    float q0 = 0.f, q1 = 0.f, q2 = 0.f, q3 = 0.f;

    int half = (n + 1) >> 1;
    int TW = gridDim.x * 8;

    for (int base = blockIdx.x * 8 + warp; base < half; base += TW) {
        int nodeA = base;
        int nodeB = base + half;
        bool hasB = nodeB < n;

        int begA = __ldg(rowptr + nodeA);
        int endA = __ldg(rowptr + nodeA + 1);
        int begB = 0, endB = 0;
        if (hasB) { begB = __ldg(rowptr + nodeB); endB = __ldg(rowptr + nodeB + 1); }

        float4 accA = __ldg((const float4*)(hs + (size_t)nodeA * DH + g));
        float4 accB = hasB ? __ldg((const float4*)(hs + (size_t)nodeB * DH + g))
                           : make_float4(0.f, 0.f, 0.f, 0.f);

        int ja = begA, jb = begB;
        // interleaved main loop: 4 loads from each list in flight together
        while (ja + 4 <= endA && jb + 4 <= endB) {
            int ia[4], ib[4];
#pragma unroll
            for (int u = 0; u < 4; u++) { ia[u] = __ldg(adj + ja + u); ib[u] = __ldg(adj + jb + u); }
            float4 va[4], vb[4];
#pragma unroll
            for (int u = 0; u < 4; u++) {
                va[u] = __ldg((const float4*)(hs + (size_t)ia[u] * DH + g));
                vb[u] = __ldg((const float4*)(hs + (size_t)ib[u] * DH + g));
            }
#pragma unroll
            for (int u = 0; u < 4; u++) {
                accA.x += va[u].x; accA.y += va[u].y; accA.z += va[u].z; accA.w += va[u].w;
                accB.x += vb[u].x; accB.y += vb[u].y; accB.z += vb[u].z; accB.w += vb[u].w;
            }
            ja += 4; jb += 4;
        }
        // drain A
        for (; ja + 4 <= endA; ja += 4) {
            int ia[4];
#pragma unroll
            for (int u = 0; u < 4; u++) ia[u] = __ldg(adj + ja + u);
            float4 va[4];
#pragma unroll
            for (int u = 0; u < 4; u++) va[u] = __ldg((const float4*)(hs + (size_t)ia[u] * DH + g));
#pragma unroll
            for (int u = 0; u < 4; u++) {
                accA.x += va[u].x; accA.y += va[u].y; accA.z += va[u].z; accA.w += va[u].w;
            }
        }
        for (; ja < endA; ja++) {
            int s = __ldg(adj + ja);
            float4 v = __ldg((const float4*)(hs + (size_t)s * DH + g));
            accA.x += v.x; accA.y += v.y; accA.z += v.z; accA.w += v.w;
        }
        // drain B
        for (; jb + 4 <= endB; jb += 4) {
            int ib[4];
#pragma unroll
            for (int u = 0; u < 4; u++) ib[u] = __ldg(adj + jb + u);
            float4 vb[4];
#pragma unroll
            for (int u = 0; u < 4; u++) vb[u] = __ldg((const float4*)(hs + (size_t)ib[u] * DH + g));
#pragma unroll
            for (int u = 0; u < 4; u++) {
                accB.x += vb[u].x; accB.y += vb[u].y; accB.z += vb[u].z; accB.w += vb[u].w;
            }
        }
        for (; jb < endB; jb++) {
            int s = __ldg(adj + jb);
            float4 v = __ldg((const float4*)(hs + (size_t)s * DH + g));
            accB.x += v.x; accB.y += v.y; accB.z += v.z; accB.w += v.w;
        }

        {
            float di = dinv[nodeA];
            float4 o = make_float4(bv.x + accA.x * di, bv.y + accA.y * di,
                                   bv.z + accA.z * di, bv.w + accA.w * di);
            *(float4*)(out + (size_t)nodeA * DH + g) = o;
            if (STATS) {
                s0 += o.x; q0 += o.x * o.x;
                s1 += o.y; q1 += o.y * o.y;
                s2 += o.z; q2 += o.z * o.z;
                s3 += o.w; q3 += o.w * o.w;
            }
        }
        if (hasB) {
            float di = dinv[nodeB];
            float4 o = make_float4(bv.x + accB.x * di, bv.y + accB.y * di,
                                   bv.z + accB.z * di, bv.w + accB.w * di);
            *(float4*)(out + (size_t)nodeB * DH + g) = o;
            if (STATS) {
                s0 += o.x; q0 += o.x * o.x;
                s1 += o.y; q1 += o.y * o.y;
                s2 += o.z; q2 += o.z * o.z;
                s3 += o.w; q3 += o.w * o.w;
            }
        }
    }

    if (STATS) {
        __shared__ float rsum[8][DH];
        __shared__ float rsq[8][DH];
        rsum[warp][g + 0] = s0; rsum[warp][g + 1] = s1;
        rsum[warp][g + 2] = s2; rsum[warp][g + 3] = s3;
        rsq[warp][g + 0] = q0; rsq[warp][g + 1] = q1;
        rsq[warp][g + 2] = q2; rsq[warp][g + 3] = q3;
        __syncthreads();
        if (tid < DH) {
            float a = 0.f, b = 0.f;
#pragma unroll
            for (int w = 0; w < 8; w++) { a += rsum[w][tid]; b += rsq[w][tid]; }
            atomicAdd(&g_sum[tid], a);
            atomicAdd(&g_sq[tid], b);
        }
    }
}

// ---------------- CSR gather aggregation D=40 + fused log_softmax ----------------
__global__ __launch_bounds__(256) void k_agg40(
    const float* __restrict__ hs, const int* __restrict__ rowptr,
    const int* __restrict__ adj, const float* __restrict__ dinv,
    const float* __restrict__ bias, float* __restrict__ out, int n)
{
    int tid = threadIdx.x;
    int warp = tid >> 5, lane = tid & 31;
    int node = blockIdx.x * 8 + warp;
    if (node >= n) return;

    float4 o = make_float4(0.f, 0.f, 0.f, 0.f);
    if (lane < 10) {
        int g = lane * 4;
        int beg = __ldg(rowptr + node);
        int end = __ldg(rowptr + node + 1);
        float4 acc = __ldg((const float4*)(hs + (size_t)node * 40 + g));
        int j = beg;
        for (; j + 8 <= end; j += 8) {
            int sx[8];
#pragma unroll
            for (int u = 0; u < 8; u++) sx[u] = __ldg(adj + j + u);
            float4 v[8];
#pragma unroll
            for (int u = 0; u < 8; u++)
                v[u] = __ldg((const float4*)(hs + (size_t)sx[u] * 40 + g));
#pragma unroll
            for (int u = 0; u < 8; u++) {
                acc.x += v[u].x; acc.y += v[u].y;
                acc.z += v[u].z; acc.w += v[u].w;
            }
        }
        for (; j < end; j++) {
            int s = __ldg(adj + j);
            float4 v = __ldg((const float4*)(hs + (size_t)s * 40 + g));
            acc.x += v.x; acc.y += v.y; acc.z += v.z; acc.w += v.w;
        }
        float di = dinv[node];
        float4 bvv = __ldg((const float4*)(bias + g));
        o = make_float4(bvv.x + acc.x * di, bvv.y + acc.y * di,
                        bvv.z + acc.z * di, bvv.w + acc.w * di);
    }

    float m = (lane < 10) ? fmaxf(fmaxf(o.x, o.y), fmaxf(o.z, o.w)) : -INFINITY;
#pragma unroll
    for (int off = 16; off > 0; off >>= 1)
        m = fmaxf(m, __shfl_xor_sync(0xffffffffu, m, off));
    float s = (lane < 10) ? (expf(o.x - m) + expf(o.y - m) + expf(o.z - m) + expf(o.w - m)) : 0.f;
#pragma unroll
    for (int off = 16; off > 0; off >>= 1)
        s += __shfl_xor_sync(0xffffffffu, s, off);
    float l = m + logf(s);
    if (lane < 10) {
        *(float4*)(out + (size_t)node * 40 + lane * 4) =
            make_float4(o.x - l, o.y - l, o.z - l, o.w - l);
    }
}

// ---------------- batchnorm finalize ----------------
__global__ void k_bnfin(const float* __restrict__ gamma, const float* __restrict__ beta, int n) {
    int c = threadIdx.x;
    float inv_n = 1.0f / (float)n;
    float mu = g_sum[c] * inv_n;
    float var = g_sq[c] * inv_n - mu * mu;
    float rstd = rsqrtf(var + 1e-5f);
    float a = gamma[c] * rstd;
    g_bna[c] = a;
    g_bnb[c] = beta[c] - mu * a;
}

// ---------------- host orchestration ----------------
extern "C" void kernel_launch(void* const* d_in, const int* in_sizes, int n_in,
                              void* d_out, int out_size)
{
    const float* x   = (const float*)d_in[0];
    const int*   ei  = (const int*)d_in[1];
    const float* W0  = (const float*)d_in[2];
    const float* b0  = (const float*)d_in[3];
    const float* W1  = (const float*)d_in[4];
    const float* b1  = (const float*)d_in[5];
    const float* W2  = (const float*)d_in[6];
    const float* b2  = (const float*)d_in[7];
    const float* g0  = (const float*)d_in[8];
    const float* bt0 = (const float*)d_in[9];
    const float* g1  = (const float*)d_in[10];
    const float* bt1 = (const float*)d_in[11];
    float* out = (float*)d_out;

    int N = in_sizes[0] / DH;
    int E = in_sizes[1] / 2;
    const int* src = ei;
    const int* dst = ei + E;

    float *dinv, *h1, *h2, *bna, *bnb;
    int *deg, *rowptr, *cursor, *adj;
    cudaGetSymbolAddress((void**)&dinv, g_dinv);
    cudaGetSymbolAddress((void**)&h1, g_h1);
    cudaGetSymbolAddress((void**)&h2, g_h2);
    cudaGetSymbolAddress((void**)&bna, g_bna);
    cudaGetSymbolAddress((void**)&bnb, g_bnb);
    cudaGetSymbolAddress((void**)&deg, g_deg);
    cudaGetSymbolAddress((void**)&rowptr, g_rowptr);
    cudaGetSymbolAddress((void**)&cursor, g_cursor);
    cudaGetSymbolAddress((void**)&adj, g_adj);

    // ---- CSR build (once) ----
    k_zero_deg<<<(N + 255) / 256, 256>>>(deg, N);
    k_count<<<(E + 255) / 256, 256>>>(dst, deg, E);
    k_scan<<<1, 1024>>>(deg, rowptr, cursor, dinv, N);
    k_fill<<<(E + 255) / 256, 256>>>(src, dst, cursor, adj, E);

    int gemm_blocks = (N + 127) / 128;
    int agg_grid = 1536;

    // ---- layer 0: conv -> agg (+bn stats) -> bn finalize ----
    gemm128<false><<<gemm_blocks, 256>>>(x, W0, h1, dinv, nullptr, nullptr, N);
    k_agg128<true><<<agg_grid, 256>>>(h1, rowptr, adj, dinv, b0, h2, N);
    k_bnfin<<<1, 128>>>(g0, bt0, N);

    // ---- layer 1: (bn0+relu fused) conv -> agg (+bn stats) -> bn finalize ----
    gemm128<true><<<gemm_blocks, 256>>>(h2, W1, h1, dinv, bna, bnb, N);
    k_agg128<true><<<agg_grid, 256>>>(h1, rowptr, adj, dinv, b1, h2, N);
    k_bnfin<<<1, 128>>>(g1, bt1, N);

    // ---- layer 2: (bn1+relu fused) conv -> agg + fused log_softmax ----
    gemm40<<<(N + 63) / 64, 256>>>(h2, W2, h1, dinv, bna, bnb, N);
    k_agg40<<<(N + 7) / 8, 256>>>(h1, rowptr, adj, dinv, b2, out, N);
}

// round 6
// speedup vs baseline: 1.0756x; 1.0756x over previous
#include <cuda_runtime.h>
#include <math.h>

#define DH 128
#define NMAX 50016
#define EMAX 800000

// ---------------- scratch (device globals; no allocation allowed) ----------------
__device__ float g_dinv[NMAX];
__device__ int   g_deg[NMAX];
__device__ int   g_rowptr[NMAX + 1];
__device__ int   g_cursor[NMAX];
__device__ int   g_adj[EMAX];
__device__ float g_h1[(size_t)NMAX * DH];   // dinv-scaled transformed features
__device__ float g_h2[(size_t)NMAX * DH];   // aggregated features
__device__ float g_sum[DH];
__device__ float g_sq[DH];
__device__ float g_bna[DH];                 // a = gamma * rstd
__device__ float g_bnb[DH];                 // b = beta - mu * a

// ---------------- CSR build ----------------
__global__ void k_zero_deg(int* deg, int n) {
    int i = blockIdx.x * blockDim.x + threadIdx.x;
    if (i < n) deg[i] = 0;
}

__global__ void k_count(const int* __restrict__ dst, int* deg, int E) {
    int e = blockIdx.x * blockDim.x + threadIdx.x;
    if (e < E) atomicAdd(&deg[dst[e]], 1);
}

// single block, 1024 threads: exclusive scan of deg -> rowptr/cursor, and dinv
__global__ __launch_bounds__(1024) void k_scan(const int* __restrict__ deg,
                                               int* rowptr, int* cursor,
                                               float* dinv, int n)
{
    __shared__ int sm[1024];
    const int T = 1024;
    int tid = threadIdx.x;
    int chunk = (n + T - 1) / T;
    int beg = tid * chunk;
    int end = min(beg + chunk, n);
    if (beg > n) beg = n;
    if (end < beg) end = beg;

    int s = 0;
    for (int i = beg; i < end; i++) s += deg[i];
    sm[tid] = s;
    __syncthreads();
    for (int off = 1; off < T; off <<= 1) {
        int v = (tid >= off) ? sm[tid - off] : 0;
        __syncthreads();
        sm[tid] += v;
        __syncthreads();
    }
    int run = sm[tid] - s;                  // exclusive prefix of this chunk
    for (int i = beg; i < end; i++) {
        int d = deg[i];
        rowptr[i] = run;
        cursor[i] = run;
        dinv[i] = rsqrtf((float)d + 1.0f);  // +1 self-loop
        run += d;
    }
    if (tid == T - 1) rowptr[n] = sm[T - 1];
}

__global__ void k_fill(const int* __restrict__ src, const int* __restrict__ dst,
                       int* cursor, int* adj, int E)
{
    int e = blockIdx.x * blockDim.x + threadIdx.x;
    if (e < E) {
        int d = dst[e];
        int p = atomicAdd(&cursor[d], 1);
        adj[p] = src[e];
    }
}

// ---------------- SGEMM: C[n,128] = op(A)[n,128] @ W[128,128], C scaled by dinv[row] ----------------
// 128x128 block tile, 256 threads, 8x8 per-thread tile with split-quad mapping:
// rows {ty*4..+3, 64+ty*4..+3} x cols {tx*4..+3, 64+tx*4..+3} (stride-4 smem reads).
// op(A) = BN ? relu(A*bna+bnb) : A.  Block 0 zeroes BN-stat accumulators.
template <bool BN>
__global__ __launch_bounds__(256) void gemm128(
    const float* __restrict__ A, const float* __restrict__ W,
    float* __restrict__ C, const float* __restrict__ dinv,
    const float* __restrict__ bna, const float* __restrict__ bnb, int nrows)
{
    if (blockIdx.x == 0 && threadIdx.x < DH) {
        g_sum[threadIdx.x] = 0.f;
        g_sq[threadIdx.x] = 0.f;
    }
    __shared__ float sA[16][128];    // transposed: sA[k][r]
    __shared__ float sW[16][128];
    int tid = threadIdx.x;
    int tx = tid & 15, ty = tid >> 4;
    int row0 = blockIdx.x * 128;

    float acc[8][8];
#pragma unroll
    for (int i = 0; i < 8; i++)
#pragma unroll
        for (int j = 0; j < 8; j++) acc[i][j] = 0.f;

    for (int kt = 0; kt < 128; kt += 16) {
        // A tile: 128 rows x 16 cols = 512 float4, two per thread
#pragma unroll
        for (int i = 0; i < 2; i++) {
            int f = tid + i * 256;
            int r = f >> 2;
            int k4 = (f & 3) * 4;
            int gr = row0 + r;
            float4 v = (gr < nrows) ? *(const float4*)(A + (size_t)gr * 128 + kt + k4)
                                    : make_float4(0.f, 0.f, 0.f, 0.f);
            if (BN) {
                int c = kt + k4;
                v.x = fmaxf(v.x * bna[c + 0] + bnb[c + 0], 0.f);
                v.y = fmaxf(v.y * bna[c + 1] + bnb[c + 1], 0.f);
                v.z = fmaxf(v.z * bna[c + 2] + bnb[c + 2], 0.f);
                v.w = fmaxf(v.w * bna[c + 3] + bnb[c + 3], 0.f);
            }
            sA[k4 + 0][r] = v.x; sA[k4 + 1][r] = v.y;
            sA[k4 + 2][r] = v.z; sA[k4 + 3][r] = v.w;
        }
        // W tile: 16 x 128 = 512 float4, two per thread
#pragma unroll
        for (int i = 0; i < 2; i++) {
            int f = tid + i * 256;
            int kr = f >> 5;
            int c4 = (f & 31) * 4;
            *(float4*)&sW[kr][c4] = *(const float4*)(W + (size_t)(kt + kr) * 128 + c4);
        }
        __syncthreads();

#pragma unroll
        for (int k = 0; k < 16; k++) {
            float a[8], w[8];
            *(float4*)&a[0] = *(float4*)&sA[k][ty * 4];
            *(float4*)&a[4] = *(float4*)&sA[k][64 + ty * 4];
            *(float4*)&w[0] = *(float4*)&sW[k][tx * 4];
            *(float4*)&w[4] = *(float4*)&sW[k][64 + tx * 4];
#pragma unroll
            for (int i = 0; i < 8; i++)
#pragma unroll
                for (int j = 0; j < 8; j++) acc[i][j] += a[i] * w[j];
        }
        __syncthreads();
    }

#pragma unroll
    for (int i = 0; i < 8; i++) {
        int r = (i < 4) ? (ty * 4 + i) : (64 + ty * 4 + i - 4);
        int gr = row0 + r;
        if (gr < nrows) {
            float di = dinv[gr];
            *(float4*)(C + (size_t)gr * 128 + tx * 4) =
                make_float4(acc[i][0] * di, acc[i][1] * di, acc[i][2] * di, acc[i][3] * di);
            *(float4*)(C + (size_t)gr * 128 + 64 + tx * 4) =
                make_float4(acc[i][4] * di, acc[i][5] * di, acc[i][6] * di, acc[i][7] * di);
        }
    }
}

// ---------------- SGEMM: C[n,40] = relu(A*bna+bnb)[n,128] @ W[128,40], scaled by dinv ----------------
__global__ __launch_bounds__(256) void gemm40(
    const float* __restrict__ A, const float* __restrict__ W,
    float* __restrict__ C, const float* __restrict__ dinv,
    const float* __restrict__ bna, const float* __restrict__ bnb, int nrows)
{
    __shared__ float sA[16][64];
    __shared__ float sW[16][40];
    int tid = threadIdx.x;
    int tx = tid & 15, ty = tid >> 4;
    int row0 = blockIdx.x * 64;

    float acc[4][3];
#pragma unroll
    for (int i = 0; i < 4; i++)
#pragma unroll
        for (int j = 0; j < 3; j++) acc[i][j] = 0.f;

    for (int kt = 0; kt < 128; kt += 16) {
        {
            int r = tid >> 2;
            int k4 = (tid & 3) * 4;
            int gr = row0 + r;
            float4 v = (gr < nrows) ? *(const float4*)(A + (size_t)gr * 128 + kt + k4)
                                    : make_float4(0.f, 0.f, 0.f, 0.f);
            int c = kt + k4;
            v.x = fmaxf(v.x * bna[c + 0] + bnb[c + 0], 0.f);
            v.y = fmaxf(v.y * bna[c + 1] + bnb[c + 1], 0.f);
            v.z = fmaxf(v.z * bna[c + 2] + bnb[c + 2], 0.f);
            v.w = fmaxf(v.w * bna[c + 3] + bnb[c + 3], 0.f);
            sA[k4 + 0][r] = v.x; sA[k4 + 1][r] = v.y;
            sA[k4 + 2][r] = v.z; sA[k4 + 3][r] = v.w;
        }
        for (int t = tid; t < 16 * 40; t += 256) {
            int kr = t / 40, c = t % 40;
            sW[kr][c] = W[(size_t)(kt + kr) * 40 + c];
        }
        __syncthreads();

#pragma unroll
        for (int k = 0; k < 16; k++) {
            float4 av = *(float4*)&sA[k][ty * 4];
            float a[4] = {av.x, av.y, av.z, av.w};
            float w0 = sW[k][tx];
            float w1 = sW[k][tx + 16];
            float w2 = (tx < 8) ? sW[k][tx + 32] : 0.f;
#pragma unroll
            for (int i = 0; i < 4; i++) {
                acc[i][0] += a[i] * w0;
                acc[i][1] += a[i] * w1;
                acc[i][2] += a[i] * w2;
            }
        }
        __syncthreads();
    }

#pragma unroll
    for (int i = 0; i < 4; i++) {
        int gr = row0 + ty * 4 + i;
        if (gr >= nrows) continue;
        float di = dinv[gr];
        C[(size_t)gr * 40 + tx]      = acc[i][0] * di;
        C[(size_t)gr * 40 + tx + 16] = acc[i][1] * di;
        if (tx < 8) C[(size_t)gr * 40 + tx + 32] = acc[i][2] * di;
    }
}

// ---------------- CSR gather aggregation, D=128 (R4 version, proven) ----------------
// Grid-stride, one warp per node per step. Register BN stats + block-level reduce.
template <bool STATS>
__global__ __launch_bounds__(256) void k_agg128(
    const float* __restrict__ hs, const int* __restrict__ rowptr,
    const int* __restrict__ adj, const float* __restrict__ dinv,
    const float* __restrict__ bias, float* __restrict__ out, int n)
{
    int tid = threadIdx.x;
    int warp = tid >> 5, lane = tid & 31;
    int g = lane * 4;
    float4 bv = __ldg((const float4*)(bias + g));

    float s0 = 0.f, s1 = 0.f, s2 = 0.f, s3 = 0.f;
    float q0 = 0.f, q1 = 0.f, q2 = 0.f, q3 = 0.f;

    for (int node = blockIdx.x * 8 + warp; node < n; node += gridDim.x * 8) {
        int beg = __ldg(rowptr + node);
        int end = __ldg(rowptr + node + 1);
        float4 acc = __ldg((const float4*)(hs + (size_t)node * DH + g));   // self-loop
        int j = beg;
        for (; j + 8 <= end; j += 8) {
            int sx[8];
#pragma unroll
            for (int u = 0; u < 8; u++) sx[u] = __ldg(adj + j + u);
            float4 v[8];
#pragma unroll
            for (int u = 0; u < 8; u++)
                v[u] = __ldg((const float4*)(hs + (size_t)sx[u] * DH + g));
#pragma unroll
            for (int u = 0; u < 8; u++) {
                acc.x += v[u].x; acc.y += v[u].y;
                acc.z += v[u].z; acc.w += v[u].w;
            }
        }
        for (; j < end; j++) {
            int s = __ldg(adj + j);
            float4 v = __ldg((const float4*)(hs + (size_t)s * DH + g));
            acc.x += v.x; acc.y += v.y; acc.z += v.z; acc.w += v.w;
        }
        float di = dinv[node];
        float4 o = make_float4(bv.x + acc.x * di, bv.y + acc.y * di,
                               bv.z + acc.z * di, bv.w + acc.w * di);
        *(float4*)(out + (size_t)node * DH + g) = o;
        if (STATS) {
            s0 += o.x; q0 += o.x * o.x;
            s1 += o.y; q1 += o.y * o.y;
            s2 += o.z; q2 += o.z * o.z;
            s3 += o.w; q3 += o.w * o.w;
        }
    }

    if (STATS) {
        __shared__ float rsum[8][DH];
        __shared__ float rsq[8][DH];
        rsum[warp][g + 0] = s0; rsum[warp][g + 1] = s1;
        rsum[warp][g + 2] = s2; rsum[warp][g + 3] = s3;
        rsq[warp][g + 0] = q0; rsq[warp][g + 1] = q1;
        rsq[warp][g + 2] = q2; rsq[warp][g + 3] = q3;
        __syncthreads();
        if (tid < DH) {
            float a = 0.f, b = 0.f;
#pragma unroll
            for (int w = 0; w < 8; w++) { a += rsum[w][tid]; b += rsq[w][tid]; }
            atomicAdd(&g_sum[tid], a);
            atomicAdd(&g_sq[tid], b);
        }
    }
}

// ---------------- CSR gather aggregation D=40 + fused log_softmax ----------------
__global__ __launch_bounds__(256) void k_agg40(
    const float* __restrict__ hs, const int* __restrict__ rowptr,
    const int* __restrict__ adj, const float* __restrict__ dinv,
    const float* __restrict__ bias, float* __restrict__ out, int n)
{
    int tid = threadIdx.x;
    int warp = tid >> 5, lane = tid & 31;
    int node = blockIdx.x * 8 + warp;
    if (node >= n) return;

    float4 o = make_float4(0.f, 0.f, 0.f, 0.f);
    if (lane < 10) {
        int g = lane * 4;
        int beg = __ldg(rowptr + node);
        int end = __ldg(rowptr + node + 1);
        float4 acc = __ldg((const float4*)(hs + (size_t)node * 40 + g));
        int j = beg;
        for (; j + 8 <= end; j += 8) {
            int sx[8];
#pragma unroll
            for (int u = 0; u < 8; u++) sx[u] = __ldg(adj + j + u);
            float4 v[8];
#pragma unroll
            for (int u = 0; u < 8; u++)
                v[u] = __ldg((const float4*)(hs + (size_t)sx[u] * 40 + g));
#pragma unroll
            for (int u = 0; u < 8; u++) {
                acc.x += v[u].x; acc.y += v[u].y;
                acc.z += v[u].z; acc.w += v[u].w;
            }
        }
        for (; j < end; j++) {
            int s = __ldg(adj + j);
            float4 v = __ldg((const float4*)(hs + (size_t)s * 40 + g));
            acc.x += v.x; acc.y += v.y; acc.z += v.z; acc.w += v.w;
        }
        float di = dinv[node];
        float4 bvv = __ldg((const float4*)(bias + g));
        o = make_float4(bvv.x + acc.x * di, bvv.y + acc.y * di,
                        bvv.z + acc.z * di, bvv.w + acc.w * di);
    }

    float m = (lane < 10) ? fmaxf(fmaxf(o.x, o.y), fmaxf(o.z, o.w)) : -INFINITY;
#pragma unroll
    for (int off = 16; off > 0; off >>= 1)
        m = fmaxf(m, __shfl_xor_sync(0xffffffffu, m, off));
    float s = (lane < 10) ? (expf(o.x - m) + expf(o.y - m) + expf(o.z - m) + expf(o.w - m)) : 0.f;
#pragma unroll
    for (int off = 16; off > 0; off >>= 1)
        s += __shfl_xor_sync(0xffffffffu, s, off);
    float l = m + logf(s);
    if (lane < 10) {
        *(float4*)(out + (size_t)node * 40 + lane * 4) =
            make_float4(o.x - l, o.y - l, o.z - l, o.w - l);
    }
}

// ---------------- batchnorm finalize ----------------
__global__ void k_bnfin(const float* __restrict__ gamma, const float* __restrict__ beta, int n) {
    int c = threadIdx.x;
    float inv_n = 1.0f / (float)n;
    float mu = g_sum[c] * inv_n;
    float var = g_sq[c] * inv_n - mu * mu;
    float rstd = rsqrtf(var + 1e-5f);
    float a = gamma[c] * rstd;
    g_bna[c] = a;
    g_bnb[c] = beta[c] - mu * a;
}

// ---------------- host orchestration ----------------
extern "C" void kernel_launch(void* const* d_in, const int* in_sizes, int n_in,
                              void* d_out, int out_size)
{
    const float* x   = (const float*)d_in[0];
    const int*   ei  = (const int*)d_in[1];
    const float* W0  = (const float*)d_in[2];
    const float* b0  = (const float*)d_in[3];
    const float* W1  = (const float*)d_in[4];
    const float* b1  = (const float*)d_in[5];
    const float* W2  = (const float*)d_in[6];
    const float* b2  = (const float*)d_in[7];
    const float* g0  = (const float*)d_in[8];
    const float* bt0 = (const float*)d_in[9];
    const float* g1  = (const float*)d_in[10];
    const float* bt1 = (const float*)d_in[11];
    float* out = (float*)d_out;

    int N = in_sizes[0] / DH;
    int E = in_sizes[1] / 2;
    const int* src = ei;
    const int* dst = ei + E;

    float *dinv, *h1, *h2, *bna, *bnb;
    int *deg, *rowptr, *cursor, *adj;
    cudaGetSymbolAddress((void**)&dinv, g_dinv);
    cudaGetSymbolAddress((void**)&h1, g_h1);
    cudaGetSymbolAddress((void**)&h2, g_h2);
    cudaGetSymbolAddress((void**)&bna, g_bna);
    cudaGetSymbolAddress((void**)&bnb, g_bnb);
    cudaGetSymbolAddress((void**)&deg, g_deg);
    cudaGetSymbolAddress((void**)&rowptr, g_rowptr);
    cudaGetSymbolAddress((void**)&cursor, g_cursor);
    cudaGetSymbolAddress((void**)&adj, g_adj);

    // ---- CSR build (once) ----
    k_zero_deg<<<(N + 255) / 256, 256>>>(deg, N);
    k_count<<<(E + 255) / 256, 256>>>(dst, deg, E);
    k_scan<<<1, 1024>>>(deg, rowptr, cursor, dinv, N);
    k_fill<<<(E + 255) / 256, 256>>>(src, dst, cursor, adj, E);

    int gemm_blocks = (N + 127) / 128;
    int agg_grid = 1536;

    // ---- layer 0: conv -> agg (+bn stats) -> bn finalize ----
    gemm128<false><<<gemm_blocks, 256>>>(x, W0, h1, dinv, nullptr, nullptr, N);
    k_agg128<true><<<agg_grid, 256>>>(h1, rowptr, adj, dinv, b0, h2, N);
    k_bnfin<<<1, 128>>>(g0, bt0, N);

    // ---- layer 1: (bn0+relu fused) conv -> agg (+bn stats) -> bn finalize ----
    gemm128<true><<<gemm_blocks, 256>>>(h2, W1, h1, dinv, bna, bnb, N);
    k_agg128<true><<<agg_grid, 256>>>(h1, rowptr, adj, dinv, b1, h2, N);
    k_bnfin<<<1, 128>>>(g1, bt1, N);

    // ---- layer 2: (bn1+relu fused) conv -> agg + fused log_softmax ----
    gemm40<<<(N + 63) / 64, 256>>>(h2, W2, h1, dinv, bna, bnb, N);
    k_agg40<<<(N + 7) / 8, 256>>>(h1, rowptr, adj, dinv, b2, out, N);
}

// round 7
// speedup vs baseline: 1.0758x; 1.0002x over previous
#include <cuda_runtime.h>
#include <cuda_fp16.h>
#include <math.h>

#define DH 128
#define NMAX 50016
#define EMAX 800000

// ---------------- scratch (device globals; no allocation allowed) ----------------
__device__ float  g_dinv[NMAX];
__device__ int    g_deg[NMAX];
__device__ int    g_rowptr[NMAX + 1];
__device__ int    g_cursor[NMAX];
__device__ int    g_adj[EMAX];
__device__ __half g_h1h[(size_t)NMAX * DH];  // fp16 dinv-scaled transformed features (gather operand)
__device__ float  g_h2[(size_t)NMAX * DH];   // aggregated features (fp32)
__device__ float  g_sum[DH];
__device__ float  g_sq[DH];
__device__ float  g_bna[DH];                 // a = gamma * rstd
__device__ float  g_bnb[DH];                 // b = beta - mu * a

// ---------------- CSR build ----------------
__global__ void k_zero_deg(int* deg, int n) {
    int i = blockIdx.x * blockDim.x + threadIdx.x;
    if (i < n) deg[i] = 0;
}

__global__ void k_count(const int* __restrict__ dst, int* deg, int E) {
    int e = blockIdx.x * blockDim.x + threadIdx.x;
    if (e < E) atomicAdd(&deg[dst[e]], 1);
}

// single block, 1024 threads: exclusive scan of deg -> rowptr/cursor, and dinv
__global__ __launch_bounds__(1024) void k_scan(const int* __restrict__ deg,
                                               int* rowptr, int* cursor,
                                               float* dinv, int n)
{
    __shared__ int sm[1024];
    const int T = 1024;
    int tid = threadIdx.x;
    int chunk = (n + T - 1) / T;
    int beg = tid * chunk;
    int end = min(beg + chunk, n);
    if (beg > n) beg = n;
    if (end < beg) end = beg;

    int s = 0;
    for (int i = beg; i < end; i++) s += deg[i];
    sm[tid] = s;
    __syncthreads();
    for (int off = 1; off < T; off <<= 1) {
        int v = (tid >= off) ? sm[tid - off] : 0;
        __syncthreads();
        sm[tid] += v;
        __syncthreads();
    }
    int run = sm[tid] - s;                  // exclusive prefix of this chunk
    for (int i = beg; i < end; i++) {
        int d = deg[i];
        rowptr[i] = run;
        cursor[i] = run;
        dinv[i] = rsqrtf((float)d + 1.0f);  // +1 self-loop
        run += d;
    }
    if (tid == T - 1) rowptr[n] = sm[T - 1];
}

__global__ void k_fill(const int* __restrict__ src, const int* __restrict__ dst,
                       int* cursor, int* adj, int E)
{
    int e = blockIdx.x * blockDim.x + threadIdx.x;
    if (e < E) {
        int d = dst[e];
        int p = atomicAdd(&cursor[d], 1);
        adj[p] = src[e];
    }
}

// ---------------- SGEMM: Ch[n,128] = fp16( dinv[row] * (op(A)[n,128] @ W[128,128]) ) ----------------
// 128x128 block tile, 256 threads, 8x8 per-thread split-quad register tile.
// op(A) = BN ? relu(A*bna+bnb) : A.  Block 0 zeroes BN-stat accumulators.
template <bool BN>
__global__ __launch_bounds__(256) void gemm128(
    const float* __restrict__ A, const float* __restrict__ W,
    __half* __restrict__ Ch, const float* __restrict__ dinv,
    const float* __restrict__ bna, const float* __restrict__ bnb, int nrows)
{
    if (blockIdx.x == 0 && threadIdx.x < DH) {
        g_sum[threadIdx.x] = 0.f;
        g_sq[threadIdx.x] = 0.f;
    }
    __shared__ float sA[16][128];    // transposed: sA[k][r]
    __shared__ float sW[16][128];
    int tid = threadIdx.x;
    int tx = tid & 15, ty = tid >> 4;
    int row0 = blockIdx.x * 128;

    float acc[8][8];
#pragma unroll
    for (int i = 0; i < 8; i++)
#pragma unroll
        for (int j = 0; j < 8; j++) acc[i][j] = 0.f;

    for (int kt = 0; kt < 128; kt += 16) {
#pragma unroll
        for (int i = 0; i < 2; i++) {
            int f = tid + i * 256;
            int r = f >> 2;
            int k4 = (f & 3) * 4;
            int gr = row0 + r;
            float4 v = (gr < nrows) ? *(const float4*)(A + (size_t)gr * 128 + kt + k4)
                                    : make_float4(0.f, 0.f, 0.f, 0.f);
            if (BN) {
                int c = kt + k4;
                v.x = fmaxf(v.x * bna[c + 0] + bnb[c + 0], 0.f);
                v.y = fmaxf(v.y * bna[c + 1] + bnb[c + 1], 0.f);
                v.z = fmaxf(v.z * bna[c + 2] + bnb[c + 2], 0.f);
                v.w = fmaxf(v.w * bna[c + 3] + bnb[c + 3], 0.f);
            }
            sA[k4 + 0][r] = v.x; sA[k4 + 1][r] = v.y;
            sA[k4 + 2][r] = v.z; sA[k4 + 3][r] = v.w;
        }
#pragma unroll
        for (int i = 0; i < 2; i++) {
            int f = tid + i * 256;
            int kr = f >> 5;
            int c4 = (f & 31) * 4;
            *(float4*)&sW[kr][c4] = *(const float4*)(W + (size_t)(kt + kr) * 128 + c4);
        }
        __syncthreads();

#pragma unroll
        for (int k = 0; k < 16; k++) {
            float a[8], w[8];
            *(float4*)&a[0] = *(float4*)&sA[k][ty * 4];
            *(float4*)&a[4] = *(float4*)&sA[k][64 + ty * 4];
            *(float4*)&w[0] = *(float4*)&sW[k][tx * 4];
            *(float4*)&w[4] = *(float4*)&sW[k][64 + tx * 4];
#pragma unroll
            for (int i = 0; i < 8; i++)
#pragma unroll
                for (int j = 0; j < 8; j++) acc[i][j] += a[i] * w[j];
        }
        __syncthreads();
    }

#pragma unroll
    for (int i = 0; i < 8; i++) {
        int r = (i < 4) ? (ty * 4 + i) : (64 + ty * 4 + i - 4);
        int gr = row0 + r;
        if (gr < nrows) {
            float di = dinv[gr];
            __half2 p0 = __floats2half2_rn(acc[i][0] * di, acc[i][1] * di);
            __half2 p1 = __floats2half2_rn(acc[i][2] * di, acc[i][3] * di);
            __half2 p2 = __floats2half2_rn(acc[i][4] * di, acc[i][5] * di);
            __half2 p3 = __floats2half2_rn(acc[i][6] * di, acc[i][7] * di);
            __half2* o0 = (__half2*)(Ch + (size_t)gr * 128 + tx * 4);
            o0[0] = p0; o0[1] = p1;
            __half2* o1 = (__half2*)(Ch + (size_t)gr * 128 + 64 + tx * 4);
            o1[0] = p2; o1[1] = p3;
        }
    }
}

// ---------------- SGEMM: Ch[n,40] = fp16( dinv * (relu(A*bna+bnb)[n,128] @ W[128,40]) ) ----------------
__global__ __launch_bounds__(256) void gemm40(
    const float* __restrict__ A, const float* __restrict__ W,
    __half* __restrict__ Ch, const float* __restrict__ dinv,
    const float* __restrict__ bna, const float* __restrict__ bnb, int nrows)
{
    __shared__ float sA[16][64];
    __shared__ float sW[16][40];
    int tid = threadIdx.x;
    int tx = tid & 15, ty = tid >> 4;
    int row0 = blockIdx.x * 64;

    float acc[4][3];
#pragma unroll
    for (int i = 0; i < 4; i++)
#pragma unroll
        for (int j = 0; j < 3; j++) acc[i][j] = 0.f;

    for (int kt = 0; kt < 128; kt += 16) {
        {
            int r = tid >> 2;
            int k4 = (tid & 3) * 4;
            int gr = row0 + r;
            float4 v = (gr < nrows) ? *(const float4*)(A + (size_t)gr * 128 + kt + k4)
                                    : make_float4(0.f, 0.f, 0.f, 0.f);
            int c = kt + k4;
            v.x = fmaxf(v.x * bna[c + 0] + bnb[c + 0], 0.f);
            v.y = fmaxf(v.y * bna[c + 1] + bnb[c + 1], 0.f);
            v.z = fmaxf(v.z * bna[c + 2] + bnb[c + 2], 0.f);
            v.w = fmaxf(v.w * bna[c + 3] + bnb[c + 3], 0.f);
            sA[k4 + 0][r] = v.x; sA[k4 + 1][r] = v.y;
            sA[k4 + 2][r] = v.z; sA[k4 + 3][r] = v.w;
        }
        for (int t = tid; t < 16 * 40; t += 256) {
            int kr = t / 40, c = t % 40;
            sW[kr][c] = W[(size_t)(kt + kr) * 40 + c];
        }
        __syncthreads();

#pragma unroll
        for (int k = 0; k < 16; k++) {
            float4 av = *(float4*)&sA[k][ty * 4];
            float a[4] = {av.x, av.y, av.z, av.w};
            float w0 = sW[k][tx];
            float w1 = sW[k][tx + 16];
            float w2 = (tx < 8) ? sW[k][tx + 32] : 0.f;
#pragma unroll
            for (int i = 0; i < 4; i++) {
                acc[i][0] += a[i] * w0;
                acc[i][1] += a[i] * w1;
                acc[i][2] += a[i] * w2;
            }
        }
        __syncthreads();
    }

#pragma unroll
    for (int i = 0; i < 4; i++) {
        int gr = row0 + ty * 4 + i;
        if (gr >= nrows) continue;
        float di = dinv[gr];
        Ch[(size_t)gr * 40 + tx]      = __float2half_rn(acc[i][0] * di);
        Ch[(size_t)gr * 40 + tx + 16] = __float2half_rn(acc[i][1] * di);
        if (tx < 8) Ch[(size_t)gr * 40 + tx + 32] = __float2half_rn(acc[i][2] * di);
    }
}

// ---------------- CSR gather aggregation, D=128, fp16 gather / fp32 accumulate ----------------
// Grid-stride, one warp per node. Register BN stats + block-level reduce.
template <bool STATS>
__global__ __launch_bounds__(256) void k_agg128(
    const __half* __restrict__ hs, const int* __restrict__ rowptr,
    const int* __restrict__ adj, const float* __restrict__ dinv,
    const float* __restrict__ bias, float* __restrict__ out, int n)
{
    int tid = threadIdx.x;
    int warp = tid >> 5, lane = tid & 31;
    int g = lane * 4;                       // feature index (halfs)
    float4 bv = __ldg((const float4*)(bias + g));

    float s0 = 0.f, s1 = 0.f, s2 = 0.f, s3 = 0.f;
    float q0 = 0.f, q1 = 0.f, q2 = 0.f, q3 = 0.f;

    for (int node = blockIdx.x * 8 + warp; node < n; node += gridDim.x * 8) {
        int beg = __ldg(rowptr + node);
        int end = __ldg(rowptr + node + 1);
        // self-loop
        float4 acc;
        {
            uint2 rw = __ldg((const uint2*)(hs + (size_t)node * DH + g));
            float2 f0 = __half22float2(*reinterpret_cast<__half2*>(&rw.x));
            float2 f1 = __half22float2(*reinterpret_cast<__half2*>(&rw.y));
            acc = make_float4(f0.x, f0.y, f1.x, f1.y);
        }
        int j = beg;
        for (; j + 8 <= end; j += 8) {
            int sx[8];
#pragma unroll
            for (int u = 0; u < 8; u++) sx[u] = __ldg(adj + j + u);
            uint2 rw[8];
#pragma unroll
            for (int u = 0; u < 8; u++)
                rw[u] = __ldg((const uint2*)(hs + (size_t)sx[u] * DH + g));
#pragma unroll
            for (int u = 0; u < 8; u++) {
                float2 f0 = __half22float2(*reinterpret_cast<__half2*>(&rw[u].x));
                float2 f1 = __half22float2(*reinterpret_cast<__half2*>(&rw[u].y));
                acc.x += f0.x; acc.y += f0.y; acc.z += f1.x; acc.w += f1.y;
            }
        }
        for (; j < end; j++) {
            int s = __ldg(adj + j);
            uint2 rw = __ldg((const uint2*)(hs + (size_t)s * DH + g));
            float2 f0 = __half22float2(*reinterpret_cast<__half2*>(&rw.x));
            float2 f1 = __half22float2(*reinterpret_cast<__half2*>(&rw.y));
            acc.x += f0.x; acc.y += f0.y; acc.z += f1.x; acc.w += f1.y;
        }
        float di = dinv[node];
        float4 o = make_float4(bv.x + acc.x * di, bv.y + acc.y * di,
                               bv.z + acc.z * di, bv.w + acc.w * di);
        *(float4*)(out + (size_t)node * DH + g) = o;
        if (STATS) {
            s0 += o.x; q0 += o.x * o.x;
            s1 += o.y; q1 += o.y * o.y;
            s2 += o.z; q2 += o.z * o.z;
            s3 += o.w; q3 += o.w * o.w;
        }
    }

    if (STATS) {
        __shared__ float rsum[8][DH];
        __shared__ float rsq[8][DH];
        rsum[warp][g + 0] = s0; rsum[warp][g + 1] = s1;
        rsum[warp][g + 2] = s2; rsum[warp][g + 3] = s3;
        rsq[warp][g + 0] = q0; rsq[warp][g + 1] = q1;
        rsq[warp][g + 2] = q2; rsq[warp][g + 3] = q3;
        __syncthreads();
        if (tid < DH) {
            float a = 0.f, b = 0.f;
#pragma unroll
            for (int w = 0; w < 8; w++) { a += rsum[w][tid]; b += rsq[w][tid]; }
            atomicAdd(&g_sum[tid], a);
            atomicAdd(&g_sq[tid], b);
        }
    }
}

// ---------------- CSR gather aggregation D=40 (fp16 gather) + fused log_softmax ----------------
__global__ __launch_bounds__(256) void k_agg40(
    const __half* __restrict__ hs, const int* __restrict__ rowptr,
    const int* __restrict__ adj, const float* __restrict__ dinv,
    const float* __restrict__ bias, float* __restrict__ out, int n)
{
    int tid = threadIdx.x;
    int warp = tid >> 5, lane = tid & 31;
    int node = blockIdx.x * 8 + warp;
    if (node >= n) return;

    float4 o = make_float4(0.f, 0.f, 0.f, 0.f);
    if (lane < 10) {
        int g = lane * 4;
        int beg = __ldg(rowptr + node);
        int end = __ldg(rowptr + node + 1);
        float4 acc;
        {
            uint2 rw = __ldg((const uint2*)(hs + (size_t)node * 40 + g));
            float2 f0 = __half22float2(*reinterpret_cast<__half2*>(&rw.x));
            float2 f1 = __half22float2(*reinterpret_cast<__half2*>(&rw.y));
            acc = make_float4(f0.x, f0.y, f1.x, f1.y);
        }
        int j = beg;
        for (; j + 8 <= end; j += 8) {
            int sx[8];
#pragma unroll
            for (int u = 0; u < 8; u++) sx[u] = __ldg(adj + j + u);
            uint2 rw[8];
#pragma unroll
            for (int u = 0; u < 8; u++)
                rw[u] = __ldg((const uint2*)(hs + (size_t)sx[u] * 40 + g));
#pragma unroll
            for (int u = 0; u < 8; u++) {
                float2 f0 = __half22float2(*reinterpret_cast<__half2*>(&rw[u].x));
                float2 f1 = __half22float2(*reinterpret_cast<__half2*>(&rw[u].y));
                acc.x += f0.x; acc.y += f0.y; acc.z += f1.x; acc.w += f1.y;
            }
        }
        for (; j < end; j++) {
            int s = __ldg(adj + j);
            uint2 rw = __ldg((const uint2*)(hs + (size_t)s * 40 + g));
            float2 f0 = __half22float2(*reinterpret_cast<__half2*>(&rw.x));
            float2 f1 = __half22float2(*reinterpret_cast<__half2*>(&rw.y));
            acc.x += f0.x; acc.y += f0.y; acc.z += f1.x; acc.w += f1.y;
        }
        float di = dinv[node];
        float4 bvv = __ldg((const float4*)(bias + g));
        o = make_float4(bvv.x + acc.x * di, bvv.y + acc.y * di,
                        bvv.z + acc.z * di, bvv.w + acc.w * di);
    }

    float m = (lane < 10) ? fmaxf(fmaxf(o.x, o.y), fmaxf(o.z, o.w)) : -INFINITY;
#pragma unroll
    for (int off = 16; off > 0; off >>= 1)
        m = fmaxf(m, __shfl_xor_sync(0xffffffffu, m, off));
    float s = (lane < 10) ? (expf(o.x - m) + expf(o.y - m) + expf(o.z - m) + expf(o.w - m)) : 0.f;
#pragma unroll
    for (int off = 16; off > 0; off >>= 1)
        s += __shfl_xor_sync(0xffffffffu, s, off);
    float l = m + logf(s);
    if (lane < 10) {
        *(float4*)(out + (size_t)node * 40 + lane * 4) =
            make_float4(o.x - l, o.y - l, o.z - l, o.w - l);
    }
}

// ---------------- batchnorm finalize ----------------
__global__ void k_bnfin(const float* __restrict__ gamma, const float* __restrict__ beta, int n) {
    int c = threadIdx.x;
    float inv_n = 1.0f / (float)n;
    float mu = g_sum[c] * inv_n;
    float var = g_sq[c] * inv_n - mu * mu;
    float rstd = rsqrtf(var + 1e-5f);
    float a = gamma[c] * rstd;
    g_bna[c] = a;
    g_bnb[c] = beta[c] - mu * a;
}

// ---------------- host orchestration ----------------
extern "C" void kernel_launch(void* const* d_in, const int* in_sizes, int n_in,
                              void* d_out, int out_size)
{
    const float* x   = (const float*)d_in[0];
    const int*   ei  = (const int*)d_in[1];
    const float* W0  = (const float*)d_in[2];
    const float* b0  = (const float*)d_in[3];
    const float* W1  = (const float*)d_in[4];
    const float* b1  = (const float*)d_in[5];
    const float* W2  = (const float*)d_in[6];
    const float* b2  = (const float*)d_in[7];
    const float* g0  = (const float*)d_in[8];
    const float* bt0 = (const float*)d_in[9];
    const float* g1  = (const float*)d_in[10];
    const float* bt1 = (const float*)d_in[11];
    float* out = (float*)d_out;

    int N = in_sizes[0] / DH;
    int E = in_sizes[1] / 2;
    const int* src = ei;
    const int* dst = ei + E;

    float *dinv, *h2, *bna, *bnb;
    __half* h1h;
    int *deg, *rowptr, *cursor, *adj;
    cudaGetSymbolAddress((void**)&dinv, g_dinv);
    cudaGetSymbolAddress((void**)&h1h, g_h1h);
    cudaGetSymbolAddress((void**)&h2, g_h2);
    cudaGetSymbolAddress((void**)&bna, g_bna);
    cudaGetSymbolAddress((void**)&bnb, g_bnb);
    cudaGetSymbolAddress((void**)&deg, g_deg);
    cudaGetSymbolAddress((void**)&rowptr, g_rowptr);
    cudaGetSymbolAddress((void**)&cursor, g_cursor);
    cudaGetSymbolAddress((void**)&adj, g_adj);

    // ---- CSR build (once) ----
    k_zero_deg<<<(N + 255) / 256, 256>>>(deg, N);
    k_count<<<(E + 255) / 256, 256>>>(dst, deg, E);
    k_scan<<<1, 1024>>>(deg, rowptr, cursor, dinv, N);
    k_fill<<<(E + 255) / 256, 256>>>(src, dst, cursor, adj, E);

    int gemm_blocks = (N + 127) / 128;
    int agg_grid = 1536;

    // ---- layer 0: conv -> agg (+bn stats) -> bn finalize ----
    gemm128<false><<<gemm_blocks, 256>>>(x, W0, h1h, dinv, nullptr, nullptr, N);
    k_agg128<true><<<agg_grid, 256>>>(h1h, rowptr, adj, dinv, b0, h2, N);
    k_bnfin<<<1, 128>>>(g0, bt0, N);

    // ---- layer 1: (bn0+relu fused) conv -> agg (+bn stats) -> bn finalize ----
    gemm128<true><<<gemm_blocks, 256>>>(h2, W1, h1h, dinv, bna, bnb, N);
    k_agg128<true><<<agg_grid, 256>>>(h1h, rowptr, adj, dinv, b1, h2, N);
    k_bnfin<<<1, 128>>>(g1, bt1, N);

    // ---- layer 2: (bn1+relu fused) conv -> agg + fused log_softmax ----
    gemm40<<<(N + 63) / 64, 256>>>(h2, W2, h1h, dinv, bna, bnb, N);
    k_agg40<<<(N + 7) / 8, 256>>>(h1h, rowptr, adj, dinv, b2, out, N);
}

// round 8
// speedup vs baseline: 1.1066x; 1.0287x over previous
#include <cuda_runtime.h>
#include <cuda_fp16.h>
#include <math.h>

#define DH 128
#define NMAX 50016
#define EMAX 800000

// ---------------- scratch (device globals; no allocation allowed) ----------------
__device__ float  g_dinv[NMAX];
__device__ int    g_deg[NMAX];
__device__ int    g_rowptr[NMAX + 1];
__device__ int    g_cursor[NMAX];
__device__ int    g_adj[EMAX];
__device__ __half g_h1h[(size_t)NMAX * DH];  // fp16 dinv-scaled transformed features (gather operand)
__device__ float  g_h2[(size_t)NMAX * DH];   // aggregated features (fp32)
__device__ float  g_sum[DH];
__device__ float  g_sq[DH];
__device__ float  g_bna[DH];                 // a = gamma * rstd
__device__ float  g_bnb[DH];                 // b = beta - mu * a

// ---------------- CSR build ----------------
__global__ void k_zero_deg(int* deg, int n) {
    int i = blockIdx.x * blockDim.x + threadIdx.x;
    if (i < n) deg[i] = 0;
}

__global__ void k_count(const int* __restrict__ dst, int* deg, int E) {
    int e = blockIdx.x * blockDim.x + threadIdx.x;
    if (e < E) atomicAdd(&deg[dst[e]], 1);
}

// single block, 1024 threads: exclusive scan of deg -> rowptr/cursor, and dinv
__global__ __launch_bounds__(1024) void k_scan(const int* __restrict__ deg,
                                               int* rowptr, int* cursor,
                                               float* dinv, int n)
{
    __shared__ int sm[1024];
    const int T = 1024;
    int tid = threadIdx.x;
    int chunk = (n + T - 1) / T;
    int beg = tid * chunk;
    int end = min(beg + chunk, n);
    if (beg > n) beg = n;
    if (end < beg) end = beg;

    int s = 0;
    for (int i = beg; i < end; i++) s += deg[i];
    sm[tid] = s;
    __syncthreads();
    for (int off = 1; off < T; off <<= 1) {
        int v = (tid >= off) ? sm[tid - off] : 0;
        __syncthreads();
        sm[tid] += v;
        __syncthreads();
    }
    int run = sm[tid] - s;                  // exclusive prefix of this chunk
    for (int i = beg; i < end; i++) {
        int d = deg[i];
        rowptr[i] = run;
        cursor[i] = run;
        dinv[i] = rsqrtf((float)d + 1.0f);  // +1 self-loop
        run += d;
    }
    if (tid == T - 1) rowptr[n] = sm[T - 1];
}

__global__ void k_fill(const int* __restrict__ src, const int* __restrict__ dst,
                       int* cursor, int* adj, int E)
{
    int e = blockIdx.x * blockDim.x + threadIdx.x;
    if (e < E) {
        int d = dst[e];
        int p = atomicAdd(&cursor[d], 1);
        adj[p] = src[e];
    }
}

// ---------------- SGEMM: Ch[n,128] = fp16( dinv[row] * (op(A)[n,128] @ W[128,128]) ) ----------------
template <bool BN>
__global__ __launch_bounds__(256) void gemm128(
    const float* __restrict__ A, const float* __restrict__ W,
    __half* __restrict__ Ch, const float* __restrict__ dinv,
    const float* __restrict__ bna, const float* __restrict__ bnb, int nrows)
{
    if (blockIdx.x == 0 && threadIdx.x < DH) {
        g_sum[threadIdx.x] = 0.f;
        g_sq[threadIdx.x] = 0.f;
    }
    __shared__ float sA[16][128];    // transposed: sA[k][r]
    __shared__ float sW[16][128];
    int tid = threadIdx.x;
    int tx = tid & 15, ty = tid >> 4;
    int row0 = blockIdx.x * 128;

    float acc[8][8];
#pragma unroll
    for (int i = 0; i < 8; i++)
#pragma unroll
        for (int j = 0; j < 8; j++) acc[i][j] = 0.f;

    for (int kt = 0; kt < 128; kt += 16) {
#pragma unroll
        for (int i = 0; i < 2; i++) {
            int f = tid + i * 256;
            int r = f >> 2;
            int k4 = (f & 3) * 4;
            int gr = row0 + r;
            float4 v = (gr < nrows) ? *(const float4*)(A + (size_t)gr * 128 + kt + k4)
                                    : make_float4(0.f, 0.f, 0.f, 0.f);
            if (BN) {
                int c = kt + k4;
                v.x = fmaxf(v.x * bna[c + 0] + bnb[c + 0], 0.f);
                v.y = fmaxf(v.y * bna[c + 1] + bnb[c + 1], 0.f);
                v.z = fmaxf(v.z * bna[c + 2] + bnb[c + 2], 0.f);
                v.w = fmaxf(v.w * bna[c + 3] + bnb[c + 3], 0.f);
            }
            sA[k4 + 0][r] = v.x; sA[k4 + 1][r] = v.y;
            sA[k4 + 2][r] = v.z; sA[k4 + 3][r] = v.w;
        }
#pragma unroll
        for (int i = 0; i < 2; i++) {
            int f = tid + i * 256;
            int kr = f >> 5;
            int c4 = (f & 31) * 4;
            *(float4*)&sW[kr][c4] = *(const float4*)(W + (size_t)(kt + kr) * 128 + c4);
        }
        __syncthreads();

#pragma unroll
        for (int k = 0; k < 16; k++) {
            float a[8], w[8];
            *(float4*)&a[0] = *(float4*)&sA[k][ty * 4];
            *(float4*)&a[4] = *(float4*)&sA[k][64 + ty * 4];
            *(float4*)&w[0] = *(float4*)&sW[k][tx * 4];
            *(float4*)&w[4] = *(float4*)&sW[k][64 + tx * 4];
#pragma unroll
            for (int i = 0; i < 8; i++)
#pragma unroll
                for (int j = 0; j < 8; j++) acc[i][j] += a[i] * w[j];
        }
        __syncthreads();
    }

#pragma unroll
    for (int i = 0; i < 8; i++) {
        int r = (i < 4) ? (ty * 4 + i) : (64 + ty * 4 + i - 4);
        int gr = row0 + r;
        if (gr < nrows) {
            float di = dinv[gr];
            __half2 p0 = __floats2half2_rn(acc[i][0] * di, acc[i][1] * di);
            __half2 p1 = __floats2half2_rn(acc[i][2] * di, acc[i][3] * di);
            __half2 p2 = __floats2half2_rn(acc[i][4] * di, acc[i][5] * di);
            __half2 p3 = __floats2half2_rn(acc[i][6] * di, acc[i][7] * di);
            __half2* o0 = (__half2*)(Ch + (size_t)gr * 128 + tx * 4);
            o0[0] = p0; o0[1] = p1;
            __half2* o1 = (__half2*)(Ch + (size_t)gr * 128 + 64 + tx * 4);
            o1[0] = p2; o1[1] = p3;
        }
    }
}

// ---------------- SGEMM: Ch[n,40] = fp16( dinv * (relu(A*bna+bnb)[n,128] @ W[128,40]) ) ----------------
__global__ __launch_bounds__(256) void gemm40(
    const float* __restrict__ A, const float* __restrict__ W,
    __half* __restrict__ Ch, const float* __restrict__ dinv,
    const float* __restrict__ bna, const float* __restrict__ bnb, int nrows)
{
    __shared__ float sA[16][64];
    __shared__ float sW[16][40];
    int tid = threadIdx.x;
    int tx = tid & 15, ty = tid >> 4;
    int row0 = blockIdx.x * 64;

    float acc[4][3];
#pragma unroll
    for (int i = 0; i < 4; i++)
#pragma unroll
        for (int j = 0; j < 3; j++) acc[i][j] = 0.f;

    for (int kt = 0; kt < 128; kt += 16) {
        {
            int r = tid >> 2;
            int k4 = (tid & 3) * 4;
            int gr = row0 + r;
            float4 v = (gr < nrows) ? *(const float4*)(A + (size_t)gr * 128 + kt + k4)
                                    : make_float4(0.f, 0.f, 0.f, 0.f);
            int c = kt + k4;
            v.x = fmaxf(v.x * bna[c + 0] + bnb[c + 0], 0.f);
            v.y = fmaxf(v.y * bna[c + 1] + bnb[c + 1], 0.f);
            v.z = fmaxf(v.z * bna[c + 2] + bnb[c + 2], 0.f);
            v.w = fmaxf(v.w * bna[c + 3] + bnb[c + 3], 0.f);
            sA[k4 + 0][r] = v.x; sA[k4 + 1][r] = v.y;
            sA[k4 + 2][r] = v.z; sA[k4 + 3][r] = v.w;
        }
        for (int t = tid; t < 16 * 40; t += 256) {
            int kr = t / 40, c = t % 40;
            sW[kr][c] = W[(size_t)(kt + kr) * 40 + c];
        }
        __syncthreads();

#pragma unroll
        for (int k = 0; k < 16; k++) {
            float4 av = *(float4*)&sA[k][ty * 4];
            float a[4] = {av.x, av.y, av.z, av.w};
            float w0 = sW[k][tx];
            float w1 = sW[k][tx + 16];
            float w2 = (tx < 8) ? sW[k][tx + 32] : 0.f;
#pragma unroll
            for (int i = 0; i < 4; i++) {
                acc[i][0] += a[i] * w0;
                acc[i][1] += a[i] * w1;
                acc[i][2] += a[i] * w2;
            }
        }
        __syncthreads();
    }

#pragma unroll
    for (int i = 0; i < 4; i++) {
        int gr = row0 + ty * 4 + i;
        if (gr >= nrows) continue;
        float di = dinv[gr];
        Ch[(size_t)gr * 40 + tx]      = __float2half_rn(acc[i][0] * di);
        Ch[(size_t)gr * 40 + tx + 16] = __float2half_rn(acc[i][1] * di);
        if (tx < 8) Ch[(size_t)gr * 40 + tx + 32] = __float2half_rn(acc[i][2] * di);
    }
}

// ---------------- CSR gather aggregation, D=128, PAIRED fp16 gathers ----------------
// One warp per node. Row = 256B fp16 = 16 lanes x 16B, so each LDG.128 serves TWO
// neighbors: lanes 0-15 -> even neighbor, lanes 16-31 -> odd neighbor. Per-lane fp32
// accumulation of 8 features; shfl_xor(16) merges even/odd partials at node end.
template <bool STATS>
__global__ __launch_bounds__(256) void k_agg128(
    const __half* __restrict__ hs, const int* __restrict__ rowptr,
    const int* __restrict__ adj, const float* __restrict__ dinv,
    const float* __restrict__ bias, float* __restrict__ out, int n)
{
    int tid = threadIdx.x;
    int warp = tid >> 5, lane = tid & 31;
    int side = lane >> 4;               // 0: even-indexed neighbors, 1: odd
    int fl = lane & 15;                 // feature lane: halfs [fl*8, fl*8+8)
    int g = fl * 8;

    float b[8];
    *(float4*)&b[0] = __ldg((const float4*)(bias + g));
    *(float4*)&b[4] = __ldg((const float4*)(bias + g + 4));

    float s[8], q[8];
#pragma unroll
    for (int i = 0; i < 8; i++) { s[i] = 0.f; q[i] = 0.f; }

    for (int node = blockIdx.x * 8 + warp; node < n; node += gridDim.x * 8) {
        int beg = __ldg(rowptr + node);
        int end = __ldg(rowptr + node + 1);

        float a[8];
        // self-loop: even side loads own row, odd side starts at zero
        if (side == 0) {
            uint4 v = __ldg((const uint4*)(hs + (size_t)node * DH + g));
            float2 f0 = __half22float2(*reinterpret_cast<__half2*>(&v.x));
            float2 f1 = __half22float2(*reinterpret_cast<__half2*>(&v.y));
            float2 f2 = __half22float2(*reinterpret_cast<__half2*>(&v.z));
            float2 f3 = __half22float2(*reinterpret_cast<__half2*>(&v.w));
            a[0] = f0.x; a[1] = f0.y; a[2] = f1.x; a[3] = f1.y;
            a[4] = f2.x; a[5] = f2.y; a[6] = f3.x; a[7] = f3.y;
        } else {
#pragma unroll
            for (int i = 0; i < 8; i++) a[i] = 0.f;
        }

        int j = beg;
        // main loop: 8 neighbors per iter, 4 LDG.128 per lane (each serves 2 rows)
        for (; j + 8 <= end; j += 8) {
            int ix[4];
#pragma unroll
            for (int u = 0; u < 4; u++) ix[u] = __ldg(adj + j + 2 * u + side);
            uint4 v[4];
#pragma unroll
            for (int u = 0; u < 4; u++)
                v[u] = __ldg((const uint4*)(hs + (size_t)ix[u] * DH + g));
#pragma unroll
            for (int u = 0; u < 4; u++) {
                float2 f0 = __half22float2(*reinterpret_cast<__half2*>(&v[u].x));
                float2 f1 = __half22float2(*reinterpret_cast<__half2*>(&v[u].y));
                float2 f2 = __half22float2(*reinterpret_cast<__half2*>(&v[u].z));
                float2 f3 = __half22float2(*reinterpret_cast<__half2*>(&v[u].w));
                a[0] += f0.x; a[1] += f0.y; a[2] += f1.x; a[3] += f1.y;
                a[4] += f2.x; a[5] += f2.y; a[6] += f3.x; a[7] += f3.y;
            }
        }
        // pair tail: 2 neighbors per iter, 1 LDG per lane
        for (; j + 2 <= end; j += 2) {
            int ix = __ldg(adj + j + side);
            uint4 v = __ldg((const uint4*)(hs + (size_t)ix * DH + g));
            float2 f0 = __half22float2(*reinterpret_cast<__half2*>(&v.x));
            float2 f1 = __half22float2(*reinterpret_cast<__half2*>(&v.y));
            float2 f2 = __half22float2(*reinterpret_cast<__half2*>(&v.z));
            float2 f3 = __half22float2(*reinterpret_cast<__half2*>(&v.w));
            a[0] += f0.x; a[1] += f0.y; a[2] += f1.x; a[3] += f1.y;
            a[4] += f2.x; a[5] += f2.y; a[6] += f3.x; a[7] += f3.y;
        }
        // odd leftover: even side only
        if (j < end && side == 0) {
            int ix = __ldg(adj + j);
            uint4 v = __ldg((const uint4*)(hs + (size_t)ix * DH + g));
            float2 f0 = __half22float2(*reinterpret_cast<__half2*>(&v.x));
            float2 f1 = __half22float2(*reinterpret_cast<__half2*>(&v.y));
            float2 f2 = __half22float2(*reinterpret_cast<__half2*>(&v.z));
            float2 f3 = __half22float2(*reinterpret_cast<__half2*>(&v.w));
            a[0] += f0.x; a[1] += f0.y; a[2] += f1.x; a[3] += f1.y;
            a[4] += f2.x; a[5] += f2.y; a[6] += f3.x; a[7] += f3.y;
        }

        // merge even/odd partial sums
#pragma unroll
        for (int i = 0; i < 8; i++)
            a[i] += __shfl_xor_sync(0xffffffffu, a[i], 16);

        if (side == 0) {
            float di = dinv[node];
            float o[8];
#pragma unroll
            for (int i = 0; i < 8; i++) o[i] = b[i] + a[i] * di;
            *(float4*)(out + (size_t)node * DH + g) =
                make_float4(o[0], o[1], o[2], o[3]);
            *(float4*)(out + (size_t)node * DH + g + 4) =
                make_float4(o[4], o[5], o[6], o[7]);
            if (STATS) {
#pragma unroll
                for (int i = 0; i < 8; i++) { s[i] += o[i]; q[i] += o[i] * o[i]; }
            }
        }
    }

    if (STATS) {
        __shared__ float rsum[8][DH];
        __shared__ float rsq[8][DH];
        if (side == 0) {
#pragma unroll
            for (int i = 0; i < 8; i++) {
                rsum[warp][g + i] = s[i];
                rsq[warp][g + i] = q[i];
            }
        }
        __syncthreads();
        if (tid < DH) {
            float aa = 0.f, bb = 0.f;
#pragma unroll
            for (int w = 0; w < 8; w++) { aa += rsum[w][tid]; bb += rsq[w][tid]; }
            atomicAdd(&g_sum[tid], aa);
            atomicAdd(&g_sq[tid], bb);
        }
    }
}

// ---------------- CSR gather aggregation D=40 (fp16 gather) + fused log_softmax ----------------
__global__ __launch_bounds__(256) void k_agg40(
    const __half* __restrict__ hs, const int* __restrict__ rowptr,
    const int* __restrict__ adj, const float* __restrict__ dinv,
    const float* __restrict__ bias, float* __restrict__ out, int n)
{
    int tid = threadIdx.x;
    int warp = tid >> 5, lane = tid & 31;
    int node = blockIdx.x * 8 + warp;
    if (node >= n) return;

    float4 o = make_float4(0.f, 0.f, 0.f, 0.f);
    if (lane < 10) {
        int g = lane * 4;
        int beg = __ldg(rowptr + node);
        int end = __ldg(rowptr + node + 1);
        float4 acc;
        {
            uint2 rw = __ldg((const uint2*)(hs + (size_t)node * 40 + g));
            float2 f0 = __half22float2(*reinterpret_cast<__half2*>(&rw.x));
            float2 f1 = __half22float2(*reinterpret_cast<__half2*>(&rw.y));
            acc = make_float4(f0.x, f0.y, f1.x, f1.y);
        }
        int j = beg;
        for (; j + 8 <= end; j += 8) {
            int sx[8];
#pragma unroll
            for (int u = 0; u < 8; u++) sx[u] = __ldg(adj + j + u);
            uint2 rw[8];
#pragma unroll
            for (int u = 0; u < 8; u++)
                rw[u] = __ldg((const uint2*)(hs + (size_t)sx[u] * 40 + g));
#pragma unroll
            for (int u = 0; u < 8; u++) {
                float2 f0 = __half22float2(*reinterpret_cast<__half2*>(&rw[u].x));
                float2 f1 = __half22float2(*reinterpret_cast<__half2*>(&rw[u].y));
                acc.x += f0.x; acc.y += f0.y; acc.z += f1.x; acc.w += f1.y;
            }
        }
        for (; j < end; j++) {
            int s = __ldg(adj + j);
            uint2 rw = __ldg((const uint2*)(hs + (size_t)s * 40 + g));
            float2 f0 = __half22float2(*reinterpret_cast<__half2*>(&rw.x));
            float2 f1 = __half22float2(*reinterpret_cast<__half2*>(&rw.y));
            acc.x += f0.x; acc.y += f0.y; acc.z += f1.x; acc.w += f1.y;
        }
        float di = dinv[node];
        float4 bvv = __ldg((const float4*)(bias + g));
        o = make_float4(bvv.x + acc.x * di, bvv.y + acc.y * di,
                        bvv.z + acc.z * di, bvv.w + acc.w * di);
    }

    float m = (lane < 10) ? fmaxf(fmaxf(o.x, o.y), fmaxf(o.z, o.w)) : -INFINITY;
#pragma unroll
    for (int off = 16; off > 0; off >>= 1)
        m = fmaxf(m, __shfl_xor_sync(0xffffffffu, m, off));
    float s = (lane < 10) ? (expf(o.x - m) + expf(o.y - m) + expf(o.z - m) + expf(o.w - m)) : 0.f;
#pragma unroll
    for (int off = 16; off > 0; off >>= 1)
        s += __shfl_xor_sync(0xffffffffu, s, off);
    float l = m + logf(s);
    if (lane < 10) {
        *(float4*)(out + (size_t)node * 40 + lane * 4) =
            make_float4(o.x - l, o.y - l, o.z - l, o.w - l);
    }
}

// ---------------- batchnorm finalize ----------------
__global__ void k_bnfin(const float* __restrict__ gamma, const float* __restrict__ beta, int n) {
    int c = threadIdx.x;
    float inv_n = 1.0f / (float)n;
    float mu = g_sum[c] * inv_n;
    float var = g_sq[c] * inv_n - mu * mu;
    float rstd = rsqrtf(var + 1e-5f);
    float a = gamma[c] * rstd;
    g_bna[c] = a;
    g_bnb[c] = beta[c] - mu * a;
}

// ---------------- host orchestration ----------------
extern "C" void kernel_launch(void* const* d_in, const int* in_sizes, int n_in,
                              void* d_out, int out_size)
{
    const float* x   = (const float*)d_in[0];
    const int*   ei  = (const int*)d_in[1];
    const float* W0  = (const float*)d_in[2];
    const float* b0  = (const float*)d_in[3];
    const float* W1  = (const float*)d_in[4];
    const float* b1  = (const float*)d_in[5];
    const float* W2  = (const float*)d_in[6];
    const float* b2  = (const float*)d_in[7];
    const float* g0  = (const float*)d_in[8];
    const float* bt0 = (const float*)d_in[9];
    const float* g1  = (const float*)d_in[10];
    const float* bt1 = (const float*)d_in[11];
    float* out = (float*)d_out;

    int N = in_sizes[0] / DH;
    int E = in_sizes[1] / 2;
    const int* src = ei;
    const int* dst = ei + E;

    float *dinv, *h2, *bna, *bnb;
    __half* h1h;
    int *deg, *rowptr, *cursor, *adj;
    cudaGetSymbolAddress((void**)&dinv, g_dinv);
    cudaGetSymbolAddress((void**)&h1h, g_h1h);
    cudaGetSymbolAddress((void**)&h2, g_h2);
    cudaGetSymbolAddress((void**)&bna, g_bna);
    cudaGetSymbolAddress((void**)&bnb, g_bnb);
    cudaGetSymbolAddress((void**)&deg, g_deg);
    cudaGetSymbolAddress((void**)&rowptr, g_rowptr);
    cudaGetSymbolAddress((void**)&cursor, g_cursor);
    cudaGetSymbolAddress((void**)&adj, g_adj);

    // ---- CSR build (once) ----
    k_zero_deg<<<(N + 255) / 256, 256>>>(deg, N);
    k_count<<<(E + 255) / 256, 256>>>(dst, deg, E);
    k_scan<<<1, 1024>>>(deg, rowptr, cursor, dinv, N);
    k_fill<<<(E + 255) / 256, 256>>>(src, dst, cursor, adj, E);

    int gemm_blocks = (N + 127) / 128;
    int agg_grid = 1536;

    // ---- layer 0: conv -> agg (+bn stats) -> bn finalize ----
    gemm128<false><<<gemm_blocks, 256>>>(x, W0, h1h, dinv, nullptr, nullptr, N);
    k_agg128<true><<<agg_grid, 256>>>(h1h, rowptr, adj, dinv, b0, h2, N);
    k_bnfin<<<1, 128>>>(g0, bt0, N);

    // ---- layer 1: (bn0+relu fused) conv -> agg (+bn stats) -> bn finalize ----
    gemm128<true><<<gemm_blocks, 256>>>(h2, W1, h1h, dinv, bna, bnb, N);
    k_agg128<true><<<agg_grid, 256>>>(h1h, rowptr, adj, dinv, b1, h2, N);
    k_bnfin<<<1, 128>>>(g1, bt1, N);

    // ---- layer 2: (bn1+relu fused) conv -> agg + fused log_softmax ----
    gemm40<<<(N + 63) / 64, 256>>>(h2, W2, h1h, dinv, bna, bnb, N);
    k_agg40<<<(N + 7) / 8, 256>>>(h1h, rowptr, adj, dinv, b2, out, N);
}

// round 9
// speedup vs baseline: 1.1080x; 1.0012x over previous
#include <cuda_runtime.h>
#include <cuda_fp16.h>
#include <math.h>

#define DH 128
#define NMAX 50016
#define EMAX 800000

// ---------------- scratch (device globals; no allocation allowed) ----------------
__device__ float  g_dinv[NMAX];
__device__ int    g_deg[NMAX];
__device__ int    g_rowptr[NMAX + 1];
__device__ int    g_cursor[NMAX];
__device__ int    g_adj[EMAX];
__device__ __half g_h1h[(size_t)NMAX * DH];  // fp16 dinv-scaled transformed features (gather operand)
__device__ float  g_h2[(size_t)NMAX * DH];   // aggregated features (fp32)
__device__ float  g_sum[DH];
__device__ float  g_sq[DH];
__device__ float  g_bna[DH];                 // a = gamma * rstd
__device__ float  g_bnb[DH];                 // b = beta - mu * a

// ---------------- CSR build ----------------
__global__ void k_zero_deg(int* deg, int n) {
    int i = blockIdx.x * blockDim.x + threadIdx.x;
    if (i < n) deg[i] = 0;
}

__global__ void k_count(const int* __restrict__ dst, int* deg, int E) {
    int e = blockIdx.x * blockDim.x + threadIdx.x;
    if (e < E) atomicAdd(&deg[dst[e]], 1);
}

// single block, 1024 threads: exclusive scan of deg -> rowptr/cursor, and dinv
__global__ __launch_bounds__(1024) void k_scan(const int* __restrict__ deg,
                                               int* rowptr, int* cursor,
                                               float* dinv, int n)
{
    __shared__ int sm[1024];
    const int T = 1024;
    int tid = threadIdx.x;
    int chunk = (n + T - 1) / T;
    int beg = tid * chunk;
    int end = min(beg + chunk, n);
    if (beg > n) beg = n;
    if (end < beg) end = beg;

    int s = 0;
    for (int i = beg; i < end; i++) s += deg[i];
    sm[tid] = s;
    __syncthreads();
    for (int off = 1; off < T; off <<= 1) {
        int v = (tid >= off) ? sm[tid - off] : 0;
        __syncthreads();
        sm[tid] += v;
        __syncthreads();
    }
    int run = sm[tid] - s;                  // exclusive prefix of this chunk
    for (int i = beg; i < end; i++) {
        int d = deg[i];
        rowptr[i] = run;
        cursor[i] = run;
        dinv[i] = rsqrtf((float)d + 1.0f);  // +1 self-loop
        run += d;
    }
    if (tid == T - 1) rowptr[n] = sm[T - 1];
}

__global__ void k_fill(const int* __restrict__ src, const int* __restrict__ dst,
                       int* cursor, int* adj, int E)
{
    int e = blockIdx.x * blockDim.x + threadIdx.x;
    if (e < E) {
        int d = dst[e];
        int p = atomicAdd(&cursor[d], 1);
        adj[p] = src[e];
    }
}

// ---------------- SGEMM: Ch[n,128] = fp16( dinv[row] * (op(A)[n,128] @ W[128,128]) ) ----------------
template <bool BN>
__global__ __launch_bounds__(256) void gemm128(
    const float* __restrict__ A, const float* __restrict__ W,
    __half* __restrict__ Ch, const float* __restrict__ dinv,
    const float* __restrict__ bna, const float* __restrict__ bnb, int nrows)
{
    if (blockIdx.x == 0 && threadIdx.x < DH) {
        g_sum[threadIdx.x] = 0.f;
        g_sq[threadIdx.x] = 0.f;
    }
    __shared__ float sA[16][128];    // transposed: sA[k][r]
    __shared__ float sW[16][128];
    int tid = threadIdx.x;
    int tx = tid & 15, ty = tid >> 4;
    int row0 = blockIdx.x * 128;

    float acc[8][8];
#pragma unroll
    for (int i = 0; i < 8; i++)
#pragma unroll
        for (int j = 0; j < 8; j++) acc[i][j] = 0.f;

    for (int kt = 0; kt < 128; kt += 16) {
#pragma unroll
        for (int i = 0; i < 2; i++) {
            int f = tid + i * 256;
            int r = f >> 2;
            int k4 = (f & 3) * 4;
            int gr = row0 + r;
            float4 v = (gr < nrows) ? *(const float4*)(A + (size_t)gr * 128 + kt + k4)
                                    : make_float4(0.f, 0.f, 0.f, 0.f);
            if (BN) {
                int c = kt + k4;
                v.x = fmaxf(v.x * bna[c + 0] + bnb[c + 0], 0.f);
                v.y = fmaxf(v.y * bna[c + 1] + bnb[c + 1], 0.f);
                v.z = fmaxf(v.z * bna[c + 2] + bnb[c + 2], 0.f);
                v.w = fmaxf(v.w * bna[c + 3] + bnb[c + 3], 0.f);
            }
            sA[k4 + 0][r] = v.x; sA[k4 + 1][r] = v.y;
            sA[k4 + 2][r] = v.z; sA[k4 + 3][r] = v.w;
        }
#pragma unroll
        for (int i = 0; i < 2; i++) {
            int f = tid + i * 256;
            int kr = f >> 5;
            int c4 = (f & 31) * 4;
            *(float4*)&sW[kr][c4] = *(const float4*)(W + (size_t)(kt + kr) * 128 + c4);
        }
        __syncthreads();

#pragma unroll
        for (int k = 0; k < 16; k++) {
            float a[8], w[8];
            *(float4*)&a[0] = *(float4*)&sA[k][ty * 4];
            *(float4*)&a[4] = *(float4*)&sA[k][64 + ty * 4];
            *(float4*)&w[0] = *(float4*)&sW[k][tx * 4];
            *(float4*)&w[4] = *(float4*)&sW[k][64 + tx * 4];
#pragma unroll
            for (int i = 0; i < 8; i++)
#pragma unroll
                for (int j = 0; j < 8; j++) acc[i][j] += a[i] * w[j];
        }
        __syncthreads();
    }

#pragma unroll
    for (int i = 0; i < 8; i++) {
        int r = (i < 4) ? (ty * 4 + i) : (64 + ty * 4 + i - 4);
        int gr = row0 + r;
        if (gr < nrows) {
            float di = dinv[gr];
            __half2 p0 = __floats2half2_rn(acc[i][0] * di, acc[i][1] * di);
            __half2 p1 = __floats2half2_rn(acc[i][2] * di, acc[i][3] * di);
            __half2 p2 = __floats2half2_rn(acc[i][4] * di, acc[i][5] * di);
            __half2 p3 = __floats2half2_rn(acc[i][6] * di, acc[i][7] * di);
            __half2* o0 = (__half2*)(Ch + (size_t)gr * 128 + tx * 4);
            o0[0] = p0; o0[1] = p1;
            __half2* o1 = (__half2*)(Ch + (size_t)gr * 128 + 64 + tx * 4);
            o1[0] = p2; o1[1] = p3;
        }
    }
}

// ---------------- SGEMM: Ch[n,40] = fp16( dinv * (relu(A*bna+bnb)[n,128] @ W[128,40]) ) ----------------
__global__ __launch_bounds__(256) void gemm40(
    const float* __restrict__ A, const float* __restrict__ W,
    __half* __restrict__ Ch, const float* __restrict__ dinv,
    const float* __restrict__ bna, const float* __restrict__ bnb, int nrows)
{
    __shared__ float sA[16][64];
    __shared__ float sW[16][40];
    int tid = threadIdx.x;
    int tx = tid & 15, ty = tid >> 4;
    int row0 = blockIdx.x * 64;

    float acc[4][3];
#pragma unroll
    for (int i = 0; i < 4; i++)
#pragma unroll
        for (int j = 0; j < 3; j++) acc[i][j] = 0.f;

    for (int kt = 0; kt < 128; kt += 16) {
        {
            int r = tid >> 2;
            int k4 = (tid & 3) * 4;
            int gr = row0 + r;
            float4 v = (gr < nrows) ? *(const float4*)(A + (size_t)gr * 128 + kt + k4)
                                    : make_float4(0.f, 0.f, 0.f, 0.f);
            int c = kt + k4;
            v.x = fmaxf(v.x * bna[c + 0] + bnb[c + 0], 0.f);
            v.y = fmaxf(v.y * bna[c + 1] + bnb[c + 1], 0.f);
            v.z = fmaxf(v.z * bna[c + 2] + bnb[c + 2], 0.f);
            v.w = fmaxf(v.w * bna[c + 3] + bnb[c + 3], 0.f);
            sA[k4 + 0][r] = v.x; sA[k4 + 1][r] = v.y;
            sA[k4 + 2][r] = v.z; sA[k4 + 3][r] = v.w;
        }
        for (int t = tid; t < 16 * 40; t += 256) {
            int kr = t / 40, c = t % 40;
            sW[kr][c] = W[(size_t)(kt + kr) * 40 + c];
        }
        __syncthreads();

#pragma unroll
        for (int k = 0; k < 16; k++) {
            float4 av = *(float4*)&sA[k][ty * 4];
            float a[4] = {av.x, av.y, av.z, av.w};
            float w0 = sW[k][tx];
            float w1 = sW[k][tx + 16];
            float w2 = (tx < 8) ? sW[k][tx + 32] : 0.f;
#pragma unroll
            for (int i = 0; i < 4; i++) {
                acc[i][0] += a[i] * w0;
                acc[i][1] += a[i] * w1;
                acc[i][2] += a[i] * w2;
            }
        }
        __syncthreads();
    }

#pragma unroll
    for (int i = 0; i < 4; i++) {
        int gr = row0 + ty * 4 + i;
        if (gr >= nrows) continue;
        float di = dinv[gr];
        Ch[(size_t)gr * 40 + tx]      = __float2half_rn(acc[i][0] * di);
        Ch[(size_t)gr * 40 + tx + 16] = __float2half_rn(acc[i][1] * di);
        if (tx < 8) Ch[(size_t)gr * 40 + tx + 32] = __float2half_rn(acc[i][2] * di);
    }
}

// ---------------- CSR gather aggregation, D=128, PAIRED fp16 gathers ----------------
// One warp per node. Row = 256B fp16 = 16 lanes x 16B, so each LDG.128 serves TWO
// neighbors: lanes 0-15 -> even neighbor, lanes 16-31 -> odd neighbor. Per-lane fp32
// accumulation of 8 features; shfl_xor(16) merges even/odd partials at node end.
template <bool STATS>
__global__ __launch_bounds__(256) void k_agg128(
    const __half* __restrict__ hs, const int* __restrict__ rowptr,
    const int* __restrict__ adj, const float* __restrict__ dinv,
    const float* __restrict__ bias, float* __restrict__ out, int n)
{
    int tid = threadIdx.x;
    int warp = tid >> 5, lane = tid & 31;
    int side = lane >> 4;               // 0: even-indexed neighbors, 1: odd
    int fl = lane & 15;                 // feature lane: halfs [fl*8, fl*8+8)
    int g = fl * 8;

    float b[8];
    *(float4*)&b[0] = __ldg((const float4*)(bias + g));
    *(float4*)&b[4] = __ldg((const float4*)(bias + g + 4));

    float s[8], q[8];
#pragma unroll
    for (int i = 0; i < 8; i++) { s[i] = 0.f; q[i] = 0.f; }

    for (int node = blockIdx.x * 8 + warp; node < n; node += gridDim.x * 8) {
        int beg = __ldg(rowptr + node);
        int end = __ldg(rowptr + node + 1);

        float a[8];
        // self-loop: even side loads own row, odd side starts at zero
        if (side == 0) {
            uint4 v = __ldg((const uint4*)(hs + (size_t)node * DH + g));
            float2 f0 = __half22float2(*reinterpret_cast<__half2*>(&v.x));
            float2 f1 = __half22float2(*reinterpret_cast<__half2*>(&v.y));
            float2 f2 = __half22float2(*reinterpret_cast<__half2*>(&v.z));
            float2 f3 = __half22float2(*reinterpret_cast<__half2*>(&v.w));
            a[0] = f0.x; a[1] = f0.y; a[2] = f1.x; a[3] = f1.y;
            a[4] = f2.x; a[5] = f2.y; a[6] = f3.x; a[7] = f3.y;
        } else {
#pragma unroll
            for (int i = 0; i < 8; i++) a[i] = 0.f;
        }

        int j = beg;
        // main loop: 8 neighbors per iter, 4 LDG.128 per lane (each serves 2 rows)
        for (; j + 8 <= end; j += 8) {
            int ix[4];
#pragma unroll
            for (int u = 0; u < 4; u++) ix[u] = __ldg(adj + j + 2 * u + side);
            uint4 v[4];
#pragma unroll
            for (int u = 0; u < 4; u++)
                v[u] = __ldg((const uint4*)(hs + (size_t)ix[u] * DH + g));
#pragma unroll
            for (int u = 0; u < 4; u++) {
                float2 f0 = __half22float2(*reinterpret_cast<__half2*>(&v[u].x));
                float2 f1 = __half22float2(*reinterpret_cast<__half2*>(&v[u].y));
                float2 f2 = __half22float2(*reinterpret_cast<__half2*>(&v[u].z));
                float2 f3 = __half22float2(*reinterpret_cast<__half2*>(&v[u].w));
                a[0] += f0.x; a[1] += f0.y; a[2] += f1.x; a[3] += f1.y;
                a[4] += f2.x; a[5] += f2.y; a[6] += f3.x; a[7] += f3.y;
            }
        }
        // pair tail: 2 neighbors per iter, 1 LDG per lane
        for (; j + 2 <= end; j += 2) {
            int ix = __ldg(adj + j + side);
            uint4 v = __ldg((const uint4*)(hs + (size_t)ix * DH + g));
            float2 f0 = __half22float2(*reinterpret_cast<__half2*>(&v.x));
            float2 f1 = __half22float2(*reinterpret_cast<__half2*>(&v.y));
            float2 f2 = __half22float2(*reinterpret_cast<__half2*>(&v.z));
            float2 f3 = __half22float2(*reinterpret_cast<__half2*>(&v.w));
            a[0] += f0.x; a[1] += f0.y; a[2] += f1.x; a[3] += f1.y;
            a[4] += f2.x; a[5] += f2.y; a[6] += f3.x; a[7] += f3.y;
        }
        // odd leftover: even side only
        if (j < end && side == 0) {
            int ix = __ldg(adj + j);
            uint4 v = __ldg((const uint4*)(hs + (size_t)ix * DH + g));
            float2 f0 = __half22float2(*reinterpret_cast<__half2*>(&v.x));
            float2 f1 = __half22float2(*reinterpret_cast<__half2*>(&v.y));
            float2 f2 = __half22float2(*reinterpret_cast<__half2*>(&v.z));
            float2 f3 = __half22float2(*reinterpret_cast<__half2*>(&v.w));
            a[0] += f0.x; a[1] += f0.y; a[2] += f1.x; a[3] += f1.y;
            a[4] += f2.x; a[5] += f2.y; a[6] += f3.x; a[7] += f3.y;
        }

        // merge even/odd partial sums
#pragma unroll
        for (int i = 0; i < 8; i++)
            a[i] += __shfl_xor_sync(0xffffffffu, a[i], 16);

        if (side == 0) {
            float di = dinv[node];
            float o[8];
#pragma unroll
            for (int i = 0; i < 8; i++) o[i] = b[i] + a[i] * di;
            *(float4*)(out + (size_t)node * DH + g) =
                make_float4(o[0], o[1], o[2], o[3]);
            *(float4*)(out + (size_t)node * DH + g + 4) =
                make_float4(o[4], o[5], o[6], o[7]);
            if (STATS) {
#pragma unroll
                for (int i = 0; i < 8; i++) { s[i] += o[i]; q[i] += o[i] * o[i]; }
            }
        }
    }

    if (STATS) {
        __shared__ float rsum[8][DH];
        __shared__ float rsq[8][DH];
        if (side == 0) {
#pragma unroll
            for (int i = 0; i < 8; i++) {
                rsum[warp][g + i] = s[i];
                rsq[warp][g + i] = q[i];
            }
        }
        __syncthreads();
        if (tid < DH) {
            float aa = 0.f, bb = 0.f;
#pragma unroll
            for (int w = 0; w < 8; w++) { aa += rsum[w][tid]; bb += rsq[w][tid]; }
            atomicAdd(&g_sum[tid], aa);
            atomicAdd(&g_sq[tid], bb);
        }
    }
}

// ---------------- CSR gather aggregation D=40 (fp16 gather) + fused log_softmax ----------------
__global__ __launch_bounds__(256) void k_agg40(
    const __half* __restrict__ hs, const int* __restrict__ rowptr,
    const int* __restrict__ adj, const float* __restrict__ dinv,
    const float* __restrict__ bias, float* __restrict__ out, int n)
{
    int tid = threadIdx.x;
    int warp = tid >> 5, lane = tid & 31;
    int node = blockIdx.x * 8 + warp;
    if (node >= n) return;

    float4 o = make_float4(0.f, 0.f, 0.f, 0.f);
    if (lane < 10) {
        int g = lane * 4;
        int beg = __ldg(rowptr + node);
        int end = __ldg(rowptr + node + 1);
        float4 acc;
        {
            uint2 rw = __ldg((const uint2*)(hs + (size_t)node * 40 + g));
            float2 f0 = __half22float2(*reinterpret_cast<__half2*>(&rw.x));
            float2 f1 = __half22float2(*reinterpret_cast<__half2*>(&rw.y));
            acc = make_float4(f0.x, f0.y, f1.x, f1.y);
        }
        int j = beg;
        for (; j + 8 <= end; j += 8) {
            int sx[8];
#pragma unroll
            for (int u = 0; u < 8; u++) sx[u] = __ldg(adj + j + u);
            uint2 rw[8];
#pragma unroll
            for (int u = 0; u < 8; u++)
                rw[u] = __ldg((const uint2*)(hs + (size_t)sx[u] * 40 + g));
#pragma unroll
            for (int u = 0; u < 8; u++) {
                float2 f0 = __half22float2(*reinterpret_cast<__half2*>(&rw[u].x));
                float2 f1 = __half22float2(*reinterpret_cast<__half2*>(&rw[u].y));
                acc.x += f0.x; acc.y += f0.y; acc.z += f1.x; acc.w += f1.y;
            }
        }
        for (; j < end; j++) {
            int s = __ldg(adj + j);
            uint2 rw = __ldg((const uint2*)(hs + (size_t)s * 40 + g));
            float2 f0 = __half22float2(*reinterpret_cast<__half2*>(&rw.x));
            float2 f1 = __half22float2(*reinterpret_cast<__half2*>(&rw.y));
            acc.x += f0.x; acc.y += f0.y; acc.z += f1.x; acc.w += f1.y;
        }
        float di = dinv[node];
        float4 bvv = __ldg((const float4*)(bias + g));
        o = make_float4(bvv.x + acc.x * di, bvv.y + acc.y * di,
                        bvv.z + acc.z * di, bvv.w + acc.w * di);
    }

    float m = (lane < 10) ? fmaxf(fmaxf(o.x, o.y), fmaxf(o.z, o.w)) : -INFINITY;
#pragma unroll
    for (int off = 16; off > 0; off >>= 1)
        m = fmaxf(m, __shfl_xor_sync(0xffffffffu, m, off));
    float s = (lane < 10) ? (expf(o.x - m) + expf(o.y - m) + expf(o.z - m) + expf(o.w - m)) : 0.f;
#pragma unroll
    for (int off = 16; off > 0; off >>= 1)
        s += __shfl_xor_sync(0xffffffffu, s, off);
    float l = m + logf(s);
    if (lane < 10) {
        *(float4*)(out + (size_t)node * 40 + lane * 4) =
            make_float4(o.x - l, o.y - l, o.z - l, o.w - l);
    }
}

// ---------------- batchnorm finalize ----------------
__global__ void k_bnfin(const float* __restrict__ gamma, const float* __restrict__ beta, int n) {
    int c = threadIdx.x;
    float inv_n = 1.0f / (float)n;
    float mu = g_sum[c] * inv_n;
    float var = g_sq[c] * inv_n - mu * mu;
    float rstd = rsqrtf(var + 1e-5f);
    float a = gamma[c] * rstd;
    g_bna[c] = a;
    g_bnb[c] = beta[c] - mu * a;
}

// ---------------- host orchestration ----------------
extern "C" void kernel_launch(void* const* d_in, const int* in_sizes, int n_in,
                              void* d_out, int out_size)
{
    const float* x   = (const float*)d_in[0];
    const int*   ei  = (const int*)d_in[1];
    const float* W0  = (const float*)d_in[2];
    const float* b0  = (const float*)d_in[3];
    const float* W1  = (const float*)d_in[4];
    const float* b1  = (const float*)d_in[5];
    const float* W2  = (const float*)d_in[6];
    const float* b2  = (const float*)d_in[7];
    const float* g0  = (const float*)d_in[8];
    const float* bt0 = (const float*)d_in[9];
    const float* g1  = (const float*)d_in[10];
    const float* bt1 = (const float*)d_in[11];
    float* out = (float*)d_out;

    int N = in_sizes[0] / DH;
    int E = in_sizes[1] / 2;
    const int* src = ei;
    const int* dst = ei + E;

    float *dinv, *h2, *bna, *bnb;
    __half* h1h;
    int *deg, *rowptr, *cursor, *adj;
    cudaGetSymbolAddress((void**)&dinv, g_dinv);
    cudaGetSymbolAddress((void**)&h1h, g_h1h);
    cudaGetSymbolAddress((void**)&h2, g_h2);
    cudaGetSymbolAddress((void**)&bna, g_bna);
    cudaGetSymbolAddress((void**)&bnb, g_bnb);
    cudaGetSymbolAddress((void**)&deg, g_deg);
    cudaGetSymbolAddress((void**)&rowptr, g_rowptr);
    cudaGetSymbolAddress((void**)&cursor, g_cursor);
    cudaGetSymbolAddress((void**)&adj, g_adj);

    // ---- CSR build (once) ----
    k_zero_deg<<<(N + 255) / 256, 256>>>(deg, N);
    k_count<<<(E + 255) / 256, 256>>>(dst, deg, E);
    k_scan<<<1, 1024>>>(deg, rowptr, cursor, dinv, N);
    k_fill<<<(E + 255) / 256, 256>>>(src, dst, cursor, adj, E);

    int gemm_blocks = (N + 127) / 128;
    int agg_grid = 1536;

    // ---- layer 0: conv -> agg (+bn stats) -> bn finalize ----
    gemm128<false><<<gemm_blocks, 256>>>(x, W0, h1h, dinv, nullptr, nullptr, N);
    k_agg128<true><<<agg_grid, 256>>>(h1h, rowptr, adj, dinv, b0, h2, N);
    k_bnfin<<<1, 128>>>(g0, bt0, N);

    // ---- layer 1: (bn0+relu fused) conv -> agg (+bn stats) -> bn finalize ----
    gemm128<true><<<gemm_blocks, 256>>>(h2, W1, h1h, dinv, bna, bnb, N);
    k_agg128<true><<<agg_grid, 256>>>(h1h, rowptr, adj, dinv, b1, h2, N);
    k_bnfin<<<1, 128>>>(g1, bt1, N);

    // ---- layer 2: (bn1+relu fused) conv -> agg + fused log_softmax ----
    gemm40<<<(N + 63) / 64, 256>>>(h2, W2, h1h, dinv, bna, bnb, N);
    k_agg40<<<(N + 7) / 8, 256>>>(h1h, rowptr, adj, dinv, b2, out, N);
}

// round 11
// speedup vs baseline: 1.2255x; 1.1061x over previous
#include <cuda_runtime.h>
#include <cuda_fp16.h>
#include <math.h>
#include <stdint.h>

#define DH 128
#define NMAX 50016
#define EMAX 800000

// ---------------- scratch (device globals; no allocation allowed) ----------------
__device__ float  g_dinv[NMAX];
__device__ int    g_deg[NMAX];
__device__ int    g_rowptr[NMAX + 1];
__device__ int    g_cursor[NMAX];
__device__ int    g_adj[EMAX];
__device__ __half g_h1h[(size_t)NMAX * DH];  // fp16 dinv-scaled transformed features (gather operand)
__device__ float  g_h2[(size_t)NMAX * DH];   // aggregated features (fp32)
__device__ float  g_sum[DH];
__device__ float  g_sq[DH];
__device__ float  g_bna[DH];                 // a = gamma * rstd
__device__ float  g_bnb[DH];                 // b = beta - mu * a

// ---------------- helpers ----------------
__device__ __forceinline__ uint32_t f2tf32(float x) {
    uint32_t u;
    asm("cvt.rna.tf32.f32 %0, %1;" : "=r"(u) : "f"(x));
    return u;
}

__device__ __forceinline__ void mma_tf32(float* c, const uint32_t* a, uint32_t b0, uint32_t b1) {
    asm volatile(
        "mma.sync.aligned.m16n8k8.row.col.f32.tf32.tf32.f32 "
        "{%0,%1,%2,%3}, {%4,%5,%6,%7}, {%8,%9}, {%0,%1,%2,%3};"
        : "+f"(c[0]), "+f"(c[1]), "+f"(c[2]), "+f"(c[3])
        : "r"(a[0]), "r"(a[1]), "r"(a[2]), "r"(a[3]), "r"(b0), "r"(b1));
}

// ---------------- CSR build ----------------
__global__ void k_count(const int* __restrict__ dst, int* deg, int E) {
    int e = blockIdx.x * blockDim.x + threadIdx.x;
    if (e < E) atomicAdd(&deg[dst[e]], 1);
}

// single block, 1024 threads: exclusive scan of deg -> rowptr/cursor, and dinv
__global__ __launch_bounds__(1024) void k_scan(const int* __restrict__ deg,
                                               int* rowptr, int* cursor,
                                               float* dinv, int n)
{
    __shared__ int sm[1024];
    const int T = 1024;
    int tid = threadIdx.x;
    int chunk = (n + T - 1) / T;
    int beg = tid * chunk;
    int end = min(beg + chunk, n);
    if (beg > n) beg = n;
    if (end < beg) end = beg;

    int s = 0;
    for (int i = beg; i < end; i++) s += deg[i];
    sm[tid] = s;
    __syncthreads();
    for (int off = 1; off < T; off <<= 1) {
        int v = (tid >= off) ? sm[tid - off] : 0;
        __syncthreads();
        sm[tid] += v;
        __syncthreads();
    }
    int run = sm[tid] - s;                  // exclusive prefix of this chunk
    for (int i = beg; i < end; i++) {
        int d = deg[i];
        rowptr[i] = run;
        cursor[i] = run;
        dinv[i] = rsqrtf((float)d + 1.0f);  // +1 self-loop
        run += d;
    }
    if (tid == T - 1) rowptr[n] = sm[T - 1];
}

__global__ void k_fill(const int* __restrict__ src, const int* __restrict__ dst,
                       int* cursor, int* adj, int E)
{
    int e = blockIdx.x * blockDim.x + threadIdx.x;
    if (e < E) {
        int d = dst[e];
        int p = atomicAdd(&cursor[d], 1);
        adj[p] = src[e];
    }
}

// ---------------- tf32 tensor-core GEMM: Ch[n,128] = fp16( dinv * (op(A) @ W) ) ----------------
// 128x128 block tile, 8 warps (4x2), each warp 32x64 via 2x8 m16n8k8 tf32 MMAs.
// op(A) = BN ? relu(A*bna+bnb) : A.  Block 0 zeroes BN-stat accumulators.
template <bool BN>
__global__ __launch_bounds__(256) void gemm128_tc(
    const float* __restrict__ A, const float* __restrict__ W,
    __half* __restrict__ Ch, const float* __restrict__ dinv,
    const float* __restrict__ bna, const float* __restrict__ bnb, int nrows)
{
    if (blockIdx.x == 0 && threadIdx.x < DH) {
        g_sum[threadIdx.x] = 0.f;
        g_sq[threadIdx.x] = 0.f;
    }
    __shared__ uint32_t sA[128][36];     // [row][k] pad->stride36: frag reads conflict-free
    __shared__ uint32_t sW[32][136];     // [k][n]  pad->stride136

    int tid = threadIdx.x;
    int lane = tid & 31, warp = tid >> 5;
    int gq = lane >> 2, tq = lane & 3;   // groupID, threadID-in-group
    int warpM = warp >> 1, warpN = warp & 1;
    int row0 = blockIdx.x * 128;

    float acc[2][8][4];
#pragma unroll
    for (int mt = 0; mt < 2; mt++)
#pragma unroll
        for (int nt = 0; nt < 8; nt++)
#pragma unroll
            for (int i = 0; i < 4; i++) acc[mt][nt][i] = 0.f;

    for (int slab = 0; slab < 4; slab++) {
        int kt = slab * 32;
        // A slab: 128 rows x 32 k  (4 float4 per thread)
#pragma unroll
        for (int i = 0; i < 4; i++) {
            int f = tid + i * 256;
            int r = f >> 3;
            int c4 = (f & 7) * 4;
            int gr = row0 + r;
            float4 v = (gr < nrows) ? *(const float4*)(A + (size_t)gr * 128 + kt + c4)
                                    : make_float4(0.f, 0.f, 0.f, 0.f);
            if (BN) {
                int c = kt + c4;
                v.x = fmaxf(v.x * bna[c + 0] + bnb[c + 0], 0.f);
                v.y = fmaxf(v.y * bna[c + 1] + bnb[c + 1], 0.f);
                v.z = fmaxf(v.z * bna[c + 2] + bnb[c + 2], 0.f);
                v.w = fmaxf(v.w * bna[c + 3] + bnb[c + 3], 0.f);
            }
            uint4 u = make_uint4(f2tf32(v.x), f2tf32(v.y), f2tf32(v.z), f2tf32(v.w));
            *(uint4*)&sA[r][c4] = u;
        }
        // W slab: 32 k x 128 n = 1024 float4 -> 4 per thread (R10 bug: was 2)
#pragma unroll
        for (int i = 0; i < 4; i++) {
            int f = tid + i * 256;
            int kr = f >> 5;
            int c4 = (f & 31) * 4;
            float4 v = *(const float4*)(W + (size_t)(kt + kr) * 128 + c4);
            uint4 u = make_uint4(f2tf32(v.x), f2tf32(v.y), f2tf32(v.z), f2tf32(v.w));
            *(uint4*)&sW[kr][c4] = u;
        }
        __syncthreads();

#pragma unroll
        for (int k8 = 0; k8 < 4; k8++) {
            int kk = k8 * 8;
            uint32_t a[2][4];
#pragma unroll
            for (int mt = 0; mt < 2; mt++) {
                int r = warpM * 32 + mt * 16 + gq;
                a[mt][0] = sA[r][kk + tq];
                a[mt][1] = sA[r + 8][kk + tq];
                a[mt][2] = sA[r][kk + tq + 4];
                a[mt][3] = sA[r + 8][kk + tq + 4];
            }
#pragma unroll
            for (int nt = 0; nt < 8; nt++) {
                int n = warpN * 64 + nt * 8 + gq;
                uint32_t b0 = sW[kk + tq][n];
                uint32_t b1 = sW[kk + tq + 4][n];
                mma_tf32(acc[0][nt], a[0], b0, b1);
                mma_tf32(acc[1][nt], a[1], b0, b1);
            }
        }
        __syncthreads();
    }

    // epilogue: c0,c1 -> row gq cols 2tq,2tq+1 ; c2,c3 -> row gq+8
#pragma unroll
    for (int mt = 0; mt < 2; mt++) {
        int r0 = row0 + warpM * 32 + mt * 16 + gq;
        int r1 = r0 + 8;
        float d0 = (r0 < nrows) ? dinv[r0] : 0.f;
        float d1 = (r1 < nrows) ? dinv[r1] : 0.f;
#pragma unroll
        for (int nt = 0; nt < 8; nt++) {
            int col = warpN * 64 + nt * 8 + 2 * tq;
            if (r0 < nrows) {
                __half2 h = __floats2half2_rn(acc[mt][nt][0] * d0, acc[mt][nt][1] * d0);
                *(__half2*)(Ch + (size_t)r0 * 128 + col) = h;
            }
            if (r1 < nrows) {
                __half2 h = __floats2half2_rn(acc[mt][nt][2] * d1, acc[mt][nt][3] * d1);
                *(__half2*)(Ch + (size_t)r1 * 128 + col) = h;
            }
        }
    }
}

// ---------------- SGEMM: Ch[n,40] = fp16( dinv * (relu(A*bna+bnb)[n,128] @ W[128,40]) ) ----------------
__global__ __launch_bounds__(256) void gemm40(
    const float* __restrict__ A, const float* __restrict__ W,
    __half* __restrict__ Ch, const float* __restrict__ dinv,
    const float* __restrict__ bna, const float* __restrict__ bnb, int nrows)
{
    __shared__ float sA[16][64];
    __shared__ float sW[16][40];
    int tid = threadIdx.x;
    int tx = tid & 15, ty = tid >> 4;
    int row0 = blockIdx.x * 64;

    float acc[4][3];
#pragma unroll
    for (int i = 0; i < 4; i++)
#pragma unroll
        for (int j = 0; j < 3; j++) acc[i][j] = 0.f;

    for (int kt = 0; kt < 128; kt += 16) {
        {
            int r = tid >> 2;
            int k4 = (tid & 3) * 4;
            int gr = row0 + r;
            float4 v = (gr < nrows) ? *(const float4*)(A + (size_t)gr * 128 + kt + k4)
                                    : make_float4(0.f, 0.f, 0.f, 0.f);
            int c = kt + k4;
            v.x = fmaxf(v.x * bna[c + 0] + bnb[c + 0], 0.f);
            v.y = fmaxf(v.y * bna[c + 1] + bnb[c + 1], 0.f);
            v.z = fmaxf(v.z * bna[c + 2] + bnb[c + 2], 0.f);
            v.w = fmaxf(v.w * bna[c + 3] + bnb[c + 3], 0.f);
            sA[k4 + 0][r] = v.x; sA[k4 + 1][r] = v.y;
            sA[k4 + 2][r] = v.z; sA[k4 + 3][r] = v.w;
        }
        for (int t = tid; t < 16 * 40; t += 256) {
            int kr = t / 40, c = t % 40;
            sW[kr][c] = W[(size_t)(kt + kr) * 40 + c];
        }
        __syncthreads();

#pragma unroll
        for (int k = 0; k < 16; k++) {
            float4 av = *(float4*)&sA[k][ty * 4];
            float a[4] = {av.x, av.y, av.z, av.w};
            float w0 = sW[k][tx];
            float w1 = sW[k][tx + 16];
            float w2 = (tx < 8) ? sW[k][tx + 32] : 0.f;
#pragma unroll
            for (int i = 0; i < 4; i++) {
                acc[i][0] += a[i] * w0;
                acc[i][1] += a[i] * w1;
                acc[i][2] += a[i] * w2;
            }
        }
        __syncthreads();
    }

#pragma unroll
    for (int i = 0; i < 4; i++) {
        int gr = row0 + ty * 4 + i;
        if (gr >= nrows) continue;
        float di = dinv[gr];
        Ch[(size_t)gr * 40 + tx]      = __float2half_rn(acc[i][0] * di);
        Ch[(size_t)gr * 40 + tx + 16] = __float2half_rn(acc[i][1] * di);
        if (tx < 8) Ch[(size_t)gr * 40 + tx + 32] = __float2half_rn(acc[i][2] * di);
    }
}

// ---------------- CSR gather aggregation, D=128, PAIRED fp16 gathers (R9, proven) ----------------
template <bool STATS>
__global__ __launch_bounds__(256) void k_agg128(
    const __half* __restrict__ hs, const int* __restrict__ rowptr,
    const int* __restrict__ adj, const float* __restrict__ dinv,
    const float* __restrict__ bias, float* __restrict__ out, int n)
{
    int tid = threadIdx.x;
    int warp = tid >> 5, lane = tid & 31;
    int side = lane >> 4;               // 0: even-indexed neighbors, 1: odd
    int fl = lane & 15;                 // feature lane: halfs [fl*8, fl*8+8)
    int g = fl * 8;

    float b[8];
    *(float4*)&b[0] = __ldg((const float4*)(bias + g));
    *(float4*)&b[4] = __ldg((const float4*)(bias + g + 4));

    float s[8], q[8];
#pragma unroll
    for (int i = 0; i < 8; i++) { s[i] = 0.f; q[i] = 0.f; }

    for (int node = blockIdx.x * 8 + warp; node < n; node += gridDim.x * 8) {
        int beg = __ldg(rowptr + node);
        int end = __ldg(rowptr + node + 1);

        float a[8];
        if (side == 0) {
            uint4 v = __ldg((const uint4*)(hs + (size_t)node * DH + g));
            float2 f0 = __half22float2(*reinterpret_cast<__half2*>(&v.x));
            float2 f1 = __half22float2(*reinterpret_cast<__half2*>(&v.y));
            float2 f2 = __half22float2(*reinterpret_cast<__half2*>(&v.z));
            float2 f3 = __half22float2(*reinterpret_cast<__half2*>(&v.w));
            a[0] = f0.x; a[1] = f0.y; a[2] = f1.x; a[3] = f1.y;
            a[4] = f2.x; a[5] = f2.y; a[6] = f3.x; a[7] = f3.y;
        } else {
#pragma unroll
            for (int i = 0; i < 8; i++) a[i] = 0.f;
        }

        int j = beg;
        for (; j + 8 <= end; j += 8) {
            int ix[4];
#pragma unroll
            for (int u = 0; u < 4; u++) ix[u] = __ldg(adj + j + 2 * u + side);
            uint4 v[4];
#pragma unroll
            for (int u = 0; u < 4; u++)
                v[u] = __ldg((const uint4*)(hs + (size_t)ix[u] * DH + g));
#pragma unroll
            for (int u = 0; u < 4; u++) {
                float2 f0 = __half22float2(*reinterpret_cast<__half2*>(&v[u].x));
                float2 f1 = __half22float2(*reinterpret_cast<__half2*>(&v[u].y));
                float2 f2 = __half22float2(*reinterpret_cast<__half2*>(&v[u].z));
                float2 f3 = __half22float2(*reinterpret_cast<__half2*>(&v[u].w));
                a[0] += f0.x; a[1] += f0.y; a[2] += f1.x; a[3] += f1.y;
                a[4] += f2.x; a[5] += f2.y; a[6] += f3.x; a[7] += f3.y;
            }
        }
        for (; j + 2 <= end; j += 2) {
            int ix = __ldg(adj + j + side);
            uint4 v = __ldg((const uint4*)(hs + (size_t)ix * DH + g));
            float2 f0 = __half22float2(*reinterpret_cast<__half2*>(&v.x));
            float2 f1 = __half22float2(*reinterpret_cast<__half2*>(&v.y));
            float2 f2 = __half22float2(*reinterpret_cast<__half2*>(&v.z));
            float2 f3 = __half22float2(*reinterpret_cast<__half2*>(&v.w));
            a[0] += f0.x; a[1] += f0.y; a[2] += f1.x; a[3] += f1.y;
            a[4] += f2.x; a[5] += f2.y; a[6] += f3.x; a[7] += f3.y;
        }
        if (j < end && side == 0) {
            int ix = __ldg(adj + j);
            uint4 v = __ldg((const uint4*)(hs + (size_t)ix * DH + g));
            float2 f0 = __half22float2(*reinterpret_cast<__half2*>(&v.x));
            float2 f1 = __half22float2(*reinterpret_cast<__half2*>(&v.y));
            float2 f2 = __half22float2(*reinterpret_cast<__half2*>(&v.z));
            float2 f3 = __half22float2(*reinterpret_cast<__half2*>(&v.w));
            a[0] += f0.x; a[1] += f0.y; a[2] += f1.x; a[3] += f1.y;
            a[4] += f2.x; a[5] += f2.y; a[6] += f3.x; a[7] += f3.y;
        }

#pragma unroll
        for (int i = 0; i < 8; i++)
            a[i] += __shfl_xor_sync(0xffffffffu, a[i], 16);

        if (side == 0) {
            float di = dinv[node];
            float o[8];
#pragma unroll
            for (int i = 0; i < 8; i++) o[i] = b[i] + a[i] * di;
            *(float4*)(out + (size_t)node * DH + g) =
                make_float4(o[0], o[1], o[2], o[3]);
            *(float4*)(out + (size_t)node * DH + g + 4) =
                make_float4(o[4], o[5], o[6], o[7]);
            if (STATS) {
#pragma unroll
                for (int i = 0; i < 8; i++) { s[i] += o[i]; q[i] += o[i] * o[i]; }
            }
        }
    }

    if (STATS) {
        __shared__ float rsum[8][DH];
        __shared__ float rsq[8][DH];
        if (side == 0) {
#pragma unroll
            for (int i = 0; i < 8; i++) {
                rsum[warp][g + i] = s[i];
                rsq[warp][g + i] = q[i];
            }
        }
        __syncthreads();
        if (tid < DH) {
            float aa = 0.f, bb = 0.f;
#pragma unroll
            for (int w = 0; w < 8; w++) { aa += rsum[w][tid]; bb += rsq[w][tid]; }
            atomicAdd(&g_sum[tid], aa);
            atomicAdd(&g_sq[tid], bb);
        }
    }
}

// ---------------- CSR gather aggregation D=40 (fp16 gather) + fused log_softmax ----------------
__global__ __launch_bounds__(256) void k_agg40(
    const __half* __restrict__ hs, const int* __restrict__ rowptr,
    const int* __restrict__ adj, const float* __restrict__ dinv,
    const float* __restrict__ bias, float* __restrict__ out, int n)
{
    int tid = threadIdx.x;
    int warp = tid >> 5, lane = tid & 31;
    int node = blockIdx.x * 8 + warp;
    if (node >= n) return;

    float4 o = make_float4(0.f, 0.f, 0.f, 0.f);
    if (lane < 10) {
        int g = lane * 4;
        int beg = __ldg(rowptr + node);
        int end = __ldg(rowptr + node + 1);
        float4 acc;
        {
            uint2 rw = __ldg((const uint2*)(hs + (size_t)node * 40 + g));
            float2 f0 = __half22float2(*reinterpret_cast<__half2*>(&rw.x));
            float2 f1 = __half22float2(*reinterpret_cast<__half2*>(&rw.y));
            acc = make_float4(f0.x, f0.y, f1.x, f1.y);
        }
        int j = beg;
        for (; j + 8 <= end; j += 8) {
            int sx[8];
#pragma unroll
            for (int u = 0; u < 8; u++) sx[u] = __ldg(adj + j + u);
            uint2 rw[8];
#pragma unroll
            for (int u = 0; u < 8; u++)
                rw[u] = __ldg((const uint2*)(hs + (size_t)sx[u] * 40 + g));
#pragma unroll
            for (int u = 0; u < 8; u++) {
                float2 f0 = __half22float2(*reinterpret_cast<__half2*>(&rw[u].x));
                float2 f1 = __half22float2(*reinterpret_cast<__half2*>(&rw[u].y));
                acc.x += f0.x; acc.y += f0.y; acc.z += f1.x; acc.w += f1.y;
            }
        }
        for (; j < end; j++) {
            int s = __ldg(adj + j);
            uint2 rw = __ldg((const uint2*)(hs + (size_t)s * 40 + g));
            float2 f0 = __half22float2(*reinterpret_cast<__half2*>(&rw.x));
            float2 f1 = __half22float2(*reinterpret_cast<__half2*>(&rw.y));
            acc.x += f0.x; acc.y += f0.y; acc.z += f1.x; acc.w += f1.y;
        }
        float di = dinv[node];
        float4 bvv = __ldg((const float4*)(bias + g));
        o = make_float4(bvv.x + acc.x * di, bvv.y + acc.y * di,
                        bvv.z + acc.z * di, bvv.w + acc.w * di);
    }

    float m = (lane < 10) ? fmaxf(fmaxf(o.x, o.y), fmaxf(o.z, o.w)) : -INFINITY;
#pragma unroll
    for (int off = 16; off > 0; off >>= 1)
        m = fmaxf(m, __shfl_xor_sync(0xffffffffu, m, off));
    float s = (lane < 10) ? (expf(o.x - m) + expf(o.y - m) + expf(o.z - m) + expf(o.w - m)) : 0.f;
#pragma unroll
    for (int off = 16; off > 0; off >>= 1)
        s += __shfl_xor_sync(0xffffffffu, s, off);
    float l = m + logf(s);
    if (lane < 10) {
        *(float4*)(out + (size_t)node * 40 + lane * 4) =
            make_float4(o.x - l, o.y - l, o.z - l, o.w - l);
    }
}

// ---------------- batchnorm finalize ----------------
__global__ void k_bnfin(const float* __restrict__ gamma, const float* __restrict__ beta, int n) {
    int c = threadIdx.x;
    float inv_n = 1.0f / (float)n;
    float mu = g_sum[c] * inv_n;
    float var = g_sq[c] * inv_n - mu * mu;
    float rstd = rsqrtf(var + 1e-5f);
    float a = gamma[c] * rstd;
    g_bna[c] = a;
    g_bnb[c] = beta[c] - mu * a;
}

// ---------------- host orchestration ----------------
extern "C" void kernel_launch(void* const* d_in, const int* in_sizes, int n_in,
                              void* d_out, int out_size)
{
    const float* x   = (const float*)d_in[0];
    const int*   ei  = (const int*)d_in[1];
    const float* W0  = (const float*)d_in[2];
    const float* b0  = (const float*)d_in[3];
    const float* W1  = (const float*)d_in[4];
    const float* b1  = (const float*)d_in[5];
    const float* W2  = (const float*)d_in[6];
    const float* b2  = (const float*)d_in[7];
    const float* g0  = (const float*)d_in[8];
    const float* bt0 = (const float*)d_in[9];
    const float* g1  = (const float*)d_in[10];
    const float* bt1 = (const float*)d_in[11];
    float* out = (float*)d_out;

    int N = in_sizes[0] / DH;
    int E = in_sizes[1] / 2;
    const int* src = ei;
    const int* dst = ei + E;

    float *dinv, *h2, *bna, *bnb;
    __half* h1h;
    int *deg, *rowptr, *cursor, *adj;
    cudaGetSymbolAddress((void**)&dinv, g_dinv);
    cudaGetSymbolAddress((void**)&h1h, g_h1h);
    cudaGetSymbolAddress((void**)&h2, g_h2);
    cudaGetSymbolAddress((void**)&bna, g_bna);
    cudaGetSymbolAddress((void**)&bnb, g_bnb);
    cudaGetSymbolAddress((void**)&deg, g_deg);
    cudaGetSymbolAddress((void**)&rowptr, g_rowptr);
    cudaGetSymbolAddress((void**)&cursor, g_cursor);
    cudaGetSymbolAddress((void**)&adj, g_adj);

    // ---- CSR build (once) ----
    cudaMemsetAsync(deg, 0, (size_t)N * sizeof(int));
    k_count<<<(E + 255) / 256, 256>>>(dst, deg, E);
    k_scan<<<1, 1024>>>(deg, rowptr, cursor, dinv, N);
    k_fill<<<(E + 255) / 256, 256>>>(src, dst, cursor, adj, E);

    int gemm_blocks = (N + 127) / 128;
    int agg_grid = 1536;

    // ---- layer 0: conv -> agg (+bn stats) -> bn finalize ----
    gemm128_tc<false><<<gemm_blocks, 256>>>(x, W0, h1h, dinv, nullptr, nullptr, N);
    k_agg128<true><<<agg_grid, 256>>>(h1h, rowptr, adj, dinv, b0, h2, N);
    k_bnfin<<<1, 128>>>(g0, bt0, N);

    // ---- layer 1: (bn0+relu fused) conv -> agg (+bn stats) -> bn finalize ----
    gemm128_tc<true><<<gemm_blocks, 256>>>(h2, W1, h1h, dinv, bna, bnb, N);
    k_agg128<true><<<agg_grid, 256>>>(h1h, rowptr, adj, dinv, b1, h2, N);
    k_bnfin<<<1, 128>>>(g1, bt1, N);

    // ---- layer 2: (bn1+relu fused) conv -> agg + fused log_softmax ----
    gemm40<<<(N + 63) / 64, 256>>>(h2, W2, h1h, dinv, bna, bnb, N);
    k_agg40<<<(N + 7) / 8, 256>>>(h1h, rowptr, adj, dinv, b2, out, N);
}

// round 12
// speedup vs baseline: 1.2664x; 1.0334x over previous
#include <cuda_runtime.h>
#include <cuda_fp16.h>
#include <math.h>
#include <stdint.h>

#define DH 128
#define NMAX 50016
#define EMAX 800000

// ---------------- scratch (device globals; no allocation allowed) ----------------
__device__ float  g_dinv[NMAX];
__device__ int    g_deg[NMAX];
__device__ int    g_rowptr[NMAX + 1];
__device__ int    g_cursor[NMAX];
__device__ int    g_adj[EMAX];
__device__ __half g_h1h[(size_t)NMAX * DH];  // fp16 dinv-scaled transformed features (gather operand)
__device__ float  g_h2[(size_t)NMAX * DH];   // aggregated features (fp32)
__device__ float  g_sum[DH];
__device__ float  g_sq[DH];
__device__ float  g_bna[DH];                 // a = gamma * rstd
__device__ float  g_bnb[DH];                 // b = beta - mu * a

// ---------------- helpers ----------------
__device__ __forceinline__ uint32_t f2tf32(float x) {
    uint32_t u;
    asm("cvt.rna.tf32.f32 %0, %1;" : "=r"(u) : "f"(x));
    return u;
}

__device__ __forceinline__ void mma_tf32(float* c, const uint32_t* a, uint32_t b0, uint32_t b1) {
    asm volatile(
        "mma.sync.aligned.m16n8k8.row.col.f32.tf32.tf32.f32 "
        "{%0,%1,%2,%3}, {%4,%5,%6,%7}, {%8,%9}, {%0,%1,%2,%3};"
        : "+f"(c[0]), "+f"(c[1]), "+f"(c[2]), "+f"(c[3])
        : "r"(a[0]), "r"(a[1]), "r"(a[2]), "r"(a[3]), "r"(b0), "r"(b1));
}

// ---------------- CSR build ----------------
__global__ void k_count(const int* __restrict__ dst, int* deg, int E) {
    int e = blockIdx.x * blockDim.x + threadIdx.x;
    if (e < E) atomicAdd(&deg[dst[e]], 1);
}

// single block, 1024 threads: exclusive scan of deg -> rowptr/cursor, and dinv
__global__ __launch_bounds__(1024) void k_scan(const int* __restrict__ deg,
                                               int* rowptr, int* cursor,
                                               float* dinv, int n)
{
    __shared__ int sm[1024];
    const int T = 1024;
    int tid = threadIdx.x;
    int chunk = (n + T - 1) / T;
    int beg = tid * chunk;
    int end = min(beg + chunk, n);
    if (beg > n) beg = n;
    if (end < beg) end = beg;

    int s = 0;
    for (int i = beg; i < end; i++) s += deg[i];
    sm[tid] = s;
    __syncthreads();
    for (int off = 1; off < T; off <<= 1) {
        int v = (tid >= off) ? sm[tid - off] : 0;
        __syncthreads();
        sm[tid] += v;
        __syncthreads();
    }
    int run = sm[tid] - s;                  // exclusive prefix of this chunk
    for (int i = beg; i < end; i++) {
        int d = deg[i];
        rowptr[i] = run;
        cursor[i] = run;
        dinv[i] = rsqrtf((float)d + 1.0f);  // +1 self-loop
        run += d;
    }
    if (tid == T - 1) rowptr[n] = sm[T - 1];
}

__global__ void k_fill(const int* __restrict__ src, const int* __restrict__ dst,
                       int* cursor, int* adj, int E)
{
    int e = blockIdx.x * blockDim.x + threadIdx.x;
    if (e < E) {
        int d = dst[e];
        int p = atomicAdd(&cursor[d], 1);
        adj[p] = src[e];
    }
}

// ---------------- tf32 tensor-core GEMM: Ch[n,128] = fp16( dinv * (op(A) @ W) ) ----------------
// BM=64 block tile x 128 cols, 8 warps (4 in M x 2 in N), each warp 16x64 via 8 m16n8k8 MMAs.
// Lower smem (26.6KB) + regs (~70) -> 3 CTAs/SM for latency hiding.
// op(A) = BN ? relu(A*bna+bnb) : A.  Block 0 zeroes BN-stat accumulators.
template <bool BN>
__global__ __launch_bounds__(256) void gemm128_tc(
    const float* __restrict__ A, const float* __restrict__ W,
    __half* __restrict__ Ch, const float* __restrict__ dinv,
    const float* __restrict__ bna, const float* __restrict__ bnb, int nrows)
{
    if (blockIdx.x == 0 && threadIdx.x < DH) {
        g_sum[threadIdx.x] = 0.f;
        g_sq[threadIdx.x] = 0.f;
    }
    __shared__ uint32_t sA[64][36];      // [row][k] pad36 -> conflict-free frag reads
    __shared__ uint32_t sW[32][136];     // [k][n]  pad136

    int tid = threadIdx.x;
    int lane = tid & 31, warp = tid >> 5;
    int gq = lane >> 2, tq = lane & 3;   // groupID, threadID-in-group
    int warpM = warp >> 1, warpN = warp & 1;   // 4 x 2
    int row0 = blockIdx.x * 64;

    float acc[8][4];
#pragma unroll
    for (int nt = 0; nt < 8; nt++)
#pragma unroll
        for (int i = 0; i < 4; i++) acc[nt][i] = 0.f;

    for (int slab = 0; slab < 4; slab++) {
        int kt = slab * 32;
        // A slab: 64 rows x 32 k = 512 float4 -> 2 per thread
#pragma unroll
        for (int i = 0; i < 2; i++) {
            int f = tid + i * 256;
            int r = f >> 3;
            int c4 = (f & 7) * 4;
            int gr = row0 + r;
            float4 v = (gr < nrows) ? *(const float4*)(A + (size_t)gr * 128 + kt + c4)
                                    : make_float4(0.f, 0.f, 0.f, 0.f);
            if (BN) {
                int c = kt + c4;
                v.x = fmaxf(v.x * bna[c + 0] + bnb[c + 0], 0.f);
                v.y = fmaxf(v.y * bna[c + 1] + bnb[c + 1], 0.f);
                v.z = fmaxf(v.z * bna[c + 2] + bnb[c + 2], 0.f);
                v.w = fmaxf(v.w * bna[c + 3] + bnb[c + 3], 0.f);
            }
            uint4 u = make_uint4(f2tf32(v.x), f2tf32(v.y), f2tf32(v.z), f2tf32(v.w));
            *(uint4*)&sA[r][c4] = u;
        }
        // W slab: 32 k x 128 n = 1024 float4 -> 4 per thread
#pragma unroll
        for (int i = 0; i < 4; i++) {
            int f = tid + i * 256;
            int kr = f >> 5;
            int c4 = (f & 31) * 4;
            float4 v = *(const float4*)(W + (size_t)(kt + kr) * 128 + c4);
            uint4 u = make_uint4(f2tf32(v.x), f2tf32(v.y), f2tf32(v.z), f2tf32(v.w));
            *(uint4*)&sW[kr][c4] = u;
        }
        __syncthreads();

#pragma unroll
        for (int k8 = 0; k8 < 4; k8++) {
            int kk = k8 * 8;
            uint32_t a[4];
            {
                int r = warpM * 16 + gq;
                a[0] = sA[r][kk + tq];
                a[1] = sA[r + 8][kk + tq];
                a[2] = sA[r][kk + tq + 4];
                a[3] = sA[r + 8][kk + tq + 4];
            }
#pragma unroll
            for (int nt = 0; nt < 8; nt++) {
                int n = warpN * 64 + nt * 8 + gq;
                uint32_t b0 = sW[kk + tq][n];
                uint32_t b1 = sW[kk + tq + 4][n];
                mma_tf32(acc[nt], a, b0, b1);
            }
        }
        __syncthreads();
    }

    // epilogue: c0,c1 -> row gq cols 2tq,2tq+1 ; c2,c3 -> row gq+8
    {
        int r0 = row0 + warpM * 16 + gq;
        int r1 = r0 + 8;
        float d0 = (r0 < nrows) ? dinv[r0] : 0.f;
        float d1 = (r1 < nrows) ? dinv[r1] : 0.f;
#pragma unroll
        for (int nt = 0; nt < 8; nt++) {
            int col = warpN * 64 + nt * 8 + 2 * tq;
            if (r0 < nrows) {
                __half2 h = __floats2half2_rn(acc[nt][0] * d0, acc[nt][1] * d0);
                *(__half2*)(Ch + (size_t)r0 * 128 + col) = h;
            }
            if (r1 < nrows) {
                __half2 h = __floats2half2_rn(acc[nt][2] * d1, acc[nt][3] * d1);
                *(__half2*)(Ch + (size_t)r1 * 128 + col) = h;
            }
        }
    }
}

// ---------------- SGEMM: Ch[n,40] = fp16( dinv * (relu(A*bna+bnb)[n,128] @ W[128,40]) ) ----------------
__global__ __launch_bounds__(256) void gemm40(
    const float* __restrict__ A, const float* __restrict__ W,
    __half* __restrict__ Ch, const float* __restrict__ dinv,
    const float* __restrict__ bna, const float* __restrict__ bnb, int nrows)
{
    __shared__ float sA[16][64];
    __shared__ float sW[16][40];
    int tid = threadIdx.x;
    int tx = tid & 15, ty = tid >> 4;
    int row0 = blockIdx.x * 64;

    float acc[4][3];
#pragma unroll
    for (int i = 0; i < 4; i++)
#pragma unroll
        for (int j = 0; j < 3; j++) acc[i][j] = 0.f;

    for (int kt = 0; kt < 128; kt += 16) {
        {
            int r = tid >> 2;
            int k4 = (tid & 3) * 4;
            int gr = row0 + r;
            float4 v = (gr < nrows) ? *(const float4*)(A + (size_t)gr * 128 + kt + k4)
                                    : make_float4(0.f, 0.f, 0.f, 0.f);
            int c = kt + k4;
            v.x = fmaxf(v.x * bna[c + 0] + bnb[c + 0], 0.f);
            v.y = fmaxf(v.y * bna[c + 1] + bnb[c + 1], 0.f);
            v.z = fmaxf(v.z * bna[c + 2] + bnb[c + 2], 0.f);
            v.w = fmaxf(v.w * bna[c + 3] + bnb[c + 3], 0.f);
            sA[k4 + 0][r] = v.x; sA[k4 + 1][r] = v.y;
            sA[k4 + 2][r] = v.z; sA[k4 + 3][r] = v.w;
        }
        for (int t = tid; t < 16 * 40; t += 256) {
            int kr = t / 40, c = t % 40;
            sW[kr][c] = W[(size_t)(kt + kr) * 40 + c];
        }
        __syncthreads();

#pragma unroll
        for (int k = 0; k < 16; k++) {
            float4 av = *(float4*)&sA[k][ty * 4];
            float a[4] = {av.x, av.y, av.z, av.w};
            float w0 = sW[k][tx];
            float w1 = sW[k][tx + 16];
            float w2 = (tx < 8) ? sW[k][tx + 32] : 0.f;
#pragma unroll
            for (int i = 0; i < 4; i++) {
                acc[i][0] += a[i] * w0;
                acc[i][1] += a[i] * w1;
                acc[i][2] += a[i] * w2;
            }
        }
        __syncthreads();
    }

#pragma unroll
    for (int i = 0; i < 4; i++) {
        int gr = row0 + ty * 4 + i;
        if (gr >= nrows) continue;
        float di = dinv[gr];
        Ch[(size_t)gr * 40 + tx]      = __float2half_rn(acc[i][0] * di);
        Ch[(size_t)gr * 40 + tx + 16] = __float2half_rn(acc[i][1] * di);
        if (tx < 8) Ch[(size_t)gr * 40 + tx + 32] = __float2half_rn(acc[i][2] * di);
    }
}

// ---------------- CSR gather aggregation, D=128, PAIRED fp16 gathers (R9, proven) ----------------
template <bool STATS>
__global__ __launch_bounds__(256) void k_agg128(
    const __half* __restrict__ hs, const int* __restrict__ rowptr,
    const int* __restrict__ adj, const float* __restrict__ dinv,
    const float* __restrict__ bias, float* __restrict__ out, int n)
{
    int tid = threadIdx.x;
    int warp = tid >> 5, lane = tid & 31;
    int side = lane >> 4;               // 0: even-indexed neighbors, 1: odd
    int fl = lane & 15;                 // feature lane: halfs [fl*8, fl*8+8)
    int g = fl * 8;

    float b[8];
    *(float4*)&b[0] = __ldg((const float4*)(bias + g));
    *(float4*)&b[4] = __ldg((const float4*)(bias + g + 4));

    float s[8], q[8];
#pragma unroll
    for (int i = 0; i < 8; i++) { s[i] = 0.f; q[i] = 0.f; }

    for (int node = blockIdx.x * 8 + warp; node < n; node += gridDim.x * 8) {
        int beg = __ldg(rowptr + node);
        int end = __ldg(rowptr + node + 1);

        float a[8];
        if (side == 0) {
            uint4 v = __ldg((const uint4*)(hs + (size_t)node * DH + g));
            float2 f0 = __half22float2(*reinterpret_cast<__half2*>(&v.x));
            float2 f1 = __half22float2(*reinterpret_cast<__half2*>(&v.y));
            float2 f2 = __half22float2(*reinterpret_cast<__half2*>(&v.z));
            float2 f3 = __half22float2(*reinterpret_cast<__half2*>(&v.w));
            a[0] = f0.x; a[1] = f0.y; a[2] = f1.x; a[3] = f1.y;
            a[4] = f2.x; a[5] = f2.y; a[6] = f3.x; a[7] = f3.y;
        } else {
#pragma unroll
            for (int i = 0; i < 8; i++) a[i] = 0.f;
        }

        int j = beg;
        for (; j + 8 <= end; j += 8) {
            int ix[4];
#pragma unroll
            for (int u = 0; u < 4; u++) ix[u] = __ldg(adj + j + 2 * u + side);
            uint4 v[4];
#pragma unroll
            for (int u = 0; u < 4; u++)
                v[u] = __ldg((const uint4*)(hs + (size_t)ix[u] * DH + g));
#pragma unroll
            for (int u = 0; u < 4; u++) {
                float2 f0 = __half22float2(*reinterpret_cast<__half2*>(&v[u].x));
                float2 f1 = __half22float2(*reinterpret_cast<__half2*>(&v[u].y));
                float2 f2 = __half22float2(*reinterpret_cast<__half2*>(&v[u].z));
                float2 f3 = __half22float2(*reinterpret_cast<__half2*>(&v[u].w));
                a[0] += f0.x; a[1] += f0.y; a[2] += f1.x; a[3] += f1.y;
                a[4] += f2.x; a[5] += f2.y; a[6] += f3.x; a[7] += f3.y;
            }
        }
        for (; j + 2 <= end; j += 2) {
            int ix = __ldg(adj + j + side);
            uint4 v = __ldg((const uint4*)(hs + (size_t)ix * DH + g));
            float2 f0 = __half22float2(*reinterpret_cast<__half2*>(&v.x));
            float2 f1 = __half22float2(*reinterpret_cast<__half2*>(&v.y));
            float2 f2 = __half22float2(*reinterpret_cast<__half2*>(&v.z));
            float2 f3 = __half22float2(*reinterpret_cast<__half2*>(&v.w));
            a[0] += f0.x; a[1] += f0.y; a[2] += f1.x; a[3] += f1.y;
            a[4] += f2.x; a[5] += f2.y; a[6] += f3.x; a[7] += f3.y;
        }
        if (j < end && side == 0) {
            int ix = __ldg(adj + j);
            uint4 v = __ldg((const uint4*)(hs + (size_t)ix * DH + g));
            float2 f0 = __half22float2(*reinterpret_cast<__half2*>(&v.x));
            float2 f1 = __half22float2(*reinterpret_cast<__half2*>(&v.y));
            float2 f2 = __half22float2(*reinterpret_cast<__half2*>(&v.z));
            float2 f3 = __half22float2(*reinterpret_cast<__half2*>(&v.w));
            a[0] += f0.x; a[1] += f0.y; a[2] += f1.x; a[3] += f1.y;
            a[4] += f2.x; a[5] += f2.y; a[6] += f3.x; a[7] += f3.y;
        }

#pragma unroll
        for (int i = 0; i < 8; i++)
            a[i] += __shfl_xor_sync(0xffffffffu, a[i], 16);

        if (side == 0) {
            float di = dinv[node];
            float o[8];
#pragma unroll
            for (int i = 0; i < 8; i++) o[i] = b[i] + a[i] * di;
            *(float4*)(out + (size_t)node * DH + g) =
                make_float4(o[0], o[1], o[2], o[3]);
            *(float4*)(out + (size_t)node * DH + g + 4) =
                make_float4(o[4], o[5], o[6], o[7]);
            if (STATS) {
#pragma unroll
                for (int i = 0; i < 8; i++) { s[i] += o[i]; q[i] += o[i] * o[i]; }
            }
        }
    }

    if (STATS) {
        __shared__ float rsum[8][DH];
        __shared__ float rsq[8][DH];
        if (side == 0) {
#pragma unroll
            for (int i = 0; i < 8; i++) {
                rsum[warp][g + i] = s[i];
                rsq[warp][g + i] = q[i];
            }
        }
        __syncthreads();
        if (tid < DH) {
            float aa = 0.f, bb = 0.f;
#pragma unroll
            for (int w = 0; w < 8; w++) { aa += rsum[w][tid]; bb += rsq[w][tid]; }
            atomicAdd(&g_sum[tid], aa);
            atomicAdd(&g_sq[tid], bb);
        }
    }
}

// ---------------- CSR gather aggregation D=40 (fp16 gather) + fused log_softmax ----------------
__global__ __launch_bounds__(256) void k_agg40(
    const __half* __restrict__ hs, const int* __restrict__ rowptr,
    const int* __restrict__ adj, const float* __restrict__ dinv,
    const float* __restrict__ bias, float* __restrict__ out, int n)
{
    int tid = threadIdx.x;
    int warp = tid >> 5, lane = tid & 31;
    int node = blockIdx.x * 8 + warp;
    if (node >= n) return;

    float4 o = make_float4(0.f, 0.f, 0.f, 0.f);
    if (lane < 10) {
        int g = lane * 4;
        int beg = __ldg(rowptr + node);
        int end = __ldg(rowptr + node + 1);
        float4 acc;
        {
            uint2 rw = __ldg((const uint2*)(hs + (size_t)node * 40 + g));
            float2 f0 = __half22float2(*reinterpret_cast<__half2*>(&rw.x));
            float2 f1 = __half22float2(*reinterpret_cast<__half2*>(&rw.y));
            acc = make_float4(f0.x, f0.y, f1.x, f1.y);
        }
        int j = beg;
        for (; j + 8 <= end; j += 8) {
            int sx[8];
#pragma unroll
            for (int u = 0; u < 8; u++) sx[u] = __ldg(adj + j + u);
            uint2 rw[8];
#pragma unroll
            for (int u = 0; u < 8; u++)
                rw[u] = __ldg((const uint2*)(hs + (size_t)sx[u] * 40 + g));
#pragma unroll
            for (int u = 0; u < 8; u++) {
                float2 f0 = __half22float2(*reinterpret_cast<__half2*>(&rw[u].x));
                float2 f1 = __half22float2(*reinterpret_cast<__half2*>(&rw[u].y));
                acc.x += f0.x; acc.y += f0.y; acc.z += f1.x; acc.w += f1.y;
            }
        }
        for (; j < end; j++) {
            int s = __ldg(adj + j);
            uint2 rw = __ldg((const uint2*)(hs + (size_t)s * 40 + g));
            float2 f0 = __half22float2(*reinterpret_cast<__half2*>(&rw.x));
            float2 f1 = __half22float2(*reinterpret_cast<__half2*>(&rw.y));
            acc.x += f0.x; acc.y += f0.y; acc.z += f1.x; acc.w += f1.y;
        }
        float di = dinv[node];
        float4 bvv = __ldg((const float4*)(bias + g));
        o = make_float4(bvv.x + acc.x * di, bvv.y + acc.y * di,
                        bvv.z + acc.z * di, bvv.w + acc.w * di);
    }

    float m = (lane < 10) ? fmaxf(fmaxf(o.x, o.y), fmaxf(o.z, o.w)) : -INFINITY;
#pragma unroll
    for (int off = 16; off > 0; off >>= 1)
        m = fmaxf(m, __shfl_xor_sync(0xffffffffu, m, off));
    float s = (lane < 10) ? (expf(o.x - m) + expf(o.y - m) + expf(o.z - m) + expf(o.w - m)) : 0.f;
#pragma unroll
    for (int off = 16; off > 0; off >>= 1)
        s += __shfl_xor_sync(0xffffffffu, s, off);
    float l = m + logf(s);
    if (lane < 10) {
        *(float4*)(out + (size_t)node * 40 + lane * 4) =
            make_float4(o.x - l, o.y - l, o.z - l, o.w - l);
    }
}

// ---------------- batchnorm finalize ----------------
__global__ void k_bnfin(const float* __restrict__ gamma, const float* __restrict__ beta, int n) {
    int c = threadIdx.x;
    float inv_n = 1.0f / (float)n;
    float mu = g_sum[c] * inv_n;
    float var = g_sq[c] * inv_n - mu * mu;
    float rstd = rsqrtf(var + 1e-5f);
    float a = gamma[c] * rstd;
    g_bna[c] = a;
    g_bnb[c] = beta[c] - mu * a;
}

// ---------------- host orchestration ----------------
extern "C" void kernel_launch(void* const* d_in, const int* in_sizes, int n_in,
                              void* d_out, int out_size)
{
    const float* x   = (const float*)d_in[0];
    const int*   ei  = (const int*)d_in[1];
    const float* W0  = (const float*)d_in[2];
    const float* b0  = (const float*)d_in[3];
    const float* W1  = (const float*)d_in[4];
    const float* b1  = (const float*)d_in[5];
    const float* W2  = (const float*)d_in[6];
    const float* b2  = (const float*)d_in[7];
    const float* g0  = (const float*)d_in[8];
    const float* bt0 = (const float*)d_in[9];
    const float* g1  = (const float*)d_in[10];
    const float* bt1 = (const float*)d_in[11];
    float* out = (float*)d_out;

    int N = in_sizes[0] / DH;
    int E = in_sizes[1] / 2;
    const int* src = ei;
    const int* dst = ei + E;

    float *dinv, *h2, *bna, *bnb;
    __half* h1h;
    int *deg, *rowptr, *cursor, *adj;
    cudaGetSymbolAddress((void**)&dinv, g_dinv);
    cudaGetSymbolAddress((void**)&h1h, g_h1h);
    cudaGetSymbolAddress((void**)&h2, g_h2);
    cudaGetSymbolAddress((void**)&bna, g_bna);
    cudaGetSymbolAddress((void**)&bnb, g_bnb);
    cudaGetSymbolAddress((void**)&deg, g_deg);
    cudaGetSymbolAddress((void**)&rowptr, g_rowptr);
    cudaGetSymbolAddress((void**)&cursor, g_cursor);
    cudaGetSymbolAddress((void**)&adj, g_adj);

    // ---- CSR build (once) ----
    cudaMemsetAsync(deg, 0, (size_t)N * sizeof(int));
    k_count<<<(E + 255) / 256, 256>>>(dst, deg, E);
    k_scan<<<1, 1024>>>(deg, rowptr, cursor, dinv, N);
    k_fill<<<(E + 255) / 256, 256>>>(src, dst, cursor, adj, E);

    int gemm_blocks = (N + 63) / 64;
    int agg_grid = 1536;

    // ---- layer 0: conv -> agg (+bn stats) -> bn finalize ----
    gemm128_tc<false><<<gemm_blocks, 256>>>(x, W0, h1h, dinv, nullptr, nullptr, N);
    k_agg128<true><<<agg_grid, 256>>>(h1h, rowptr, adj, dinv, b0, h2, N);
    k_bnfin<<<1, 128>>>(g0, bt0, N);

    // ---- layer 1: (bn0+relu fused) conv -> agg (+bn stats) -> bn finalize ----
    gemm128_tc<true><<<gemm_blocks, 256>>>(h2, W1, h1h, dinv, bna, bnb, N);
    k_agg128<true><<<agg_grid, 256>>>(h1h, rowptr, adj, dinv, b1, h2, N);
    k_bnfin<<<1, 128>>>(g1, bt1, N);

    // ---- layer 2: (bn1+relu fused) conv -> agg + fused log_softmax ----
    gemm40<<<gemm_blocks, 256>>>(h2, W2, h1h, dinv, bna, bnb, N);
    k_agg40<<<(N + 7) / 8, 256>>>(h1h, rowptr, adj, dinv, b2, out, N);
}